// round 11
// baseline (speedup 1.0000x reference)
#include <cuda_runtime.h>

// Problem dimensions
static constexpr int NB = 512;   // batch
static constexpr int NT = 512;   // time
static constexpr int NOBS = 64;  // obs dim
static constexpr int NH = 256;   // hidden
static constexpr int NG = 1024;  // 4*H
static constexpr int NLAT = 16;  // latent
static constexpr int NBLK = 128; // persistent grid (8 batch-tiles x 16 col-tiles)

// ---------------- scratch (device globals; no allocation allowed) ----------
__device__ float g_xp[(size_t)NT * NB * NH];   // [t*NB+b][h] = leaky(x@Wip+bip)
__device__ float g_gx[(size_t)NT * NB * NG];   // [t*NB+b][4j+g] = xp@Wi_e + b_e
__device__ float g_Wr_ie[NH * NG];             // Wi_e reordered: [k][4j+g]
__device__ float g_Wr_he[NH * NG];             // Wh_e reordered
__device__ float g_Wr_d[NH * NG];              // (Wi_d + Wh_d) reordered
__device__ float g_br_d[NG];                   // b_d reordered
__device__ float g_h[2][NB * NH];              // ping-pong hidden state
__device__ int   g_len[NB];                    // per-row valid length (prefix mask)
__device__ unsigned g_flag[8][16 * 32];        // per-(group,block) step flags, 128B stride

// ---------------- helpers ---------------------------------------------------
union F2U { unsigned long long u; float f[2]; };

__device__ __forceinline__ void fma2(unsigned long long& d, unsigned long long a,
                                     unsigned long long b) {
    asm("fma.rn.f32x2 %0, %1, %2, %0;" : "+l"(d) : "l"(a), "l"(b));
}

__device__ __forceinline__ unsigned long long dupr(float x) {
    unsigned long long r;
    asm("mov.b64 %0, {%1, %1};" : "=l"(r) : "f"(x));
    return r;
}

__device__ __forceinline__ float fsig(float x) {
    return __fdividef(1.0f, 1.0f + __expf(-x));
}
__device__ __forceinline__ float ftanh(float x) {
    return 1.0f - __fdividef(2.0f, __expf(2.0f * x) + 1.0f);
}

// Atomic-free group barrier: each of the 16 blocks sharing batch-tile gid
// release-stores the step target into its own slot (publishes its h writes,
// no MEMBAR/atomics); threads 0-15 poll the 16 slots in parallel.
__device__ __forceinline__ void flag_barrier(int gid, int myslot, unsigned target) {
    __syncthreads();
    if (threadIdx.x == 0)
        asm volatile("st.release.gpu.global.b32 [%0], %1;"
                     :: "l"(&g_flag[gid][myslot * 32]), "r"(target) : "memory");
    if (threadIdx.x < 16) {
        unsigned cur;
        do {
            asm volatile("ld.acquire.gpu.global.b32 %0, [%1];"
                         : "=r"(cur) : "l"(&g_flag[gid][threadIdx.x * 32]) : "memory");
        } while ((int)(cur - target) < 0);
    }
    __syncthreads();
}

// ---------------- setup: weight reorder + mask lengths + flag reset ----------
__global__ void k_setup(const void* __restrict__ mask,
                        const float* __restrict__ Wi_e, const float* __restrict__ Wh_e,
                        const float* __restrict__ Wi_d, const float* __restrict__ Wh_d,
                        const float* __restrict__ b_d) {
    const int idx = blockIdx.x * 256 + threadIdx.x;   // grid 1024 x 256 = NH*NG
    {
        int k = idx >> 10, c = idx & 1023;
        int g = c & 3, j = c >> 2;
        int src = k * NG + g * NH + j;
        g_Wr_ie[idx] = Wi_e[src];
        g_Wr_he[idx] = Wh_e[src];
        g_Wr_d[idx]  = Wi_d[src] + Wh_d[src];   // decoder input == hidden -> fold
    }
    if (idx < NG) {
        int g = idx & 3, j = idx >> 2;
        g_br_d[idx] = b_d[g * NH + j];
    }
    if (idx < 8 * 16 * 32) ((unsigned*)g_flag)[idx] = 0u;
    // lengths: blocks [0, NB) each count one mask row
    if (blockIdx.x < NB) {
        const int b = blockIdx.x, tid = threadIdx.x;
        // mask[0][0] is guaranteed true; int32 read of a u8-bool row front is 0x01010101
        const bool u8 = (((const int*)mask)[0] != 1);
        int cnt = 0;
        for (int t = tid; t < NT; t += 256)
            cnt += u8 ? (((const unsigned char*)mask)[(size_t)b * NT + t] != 0)
                      : (((const int*)mask)[(size_t)b * NT + t] != 0);
#pragma unroll
        for (int off = 16; off; off >>= 1) cnt += __shfl_xor_sync(0xffffffffu, cnt, off);
        __shared__ int sred[8];
        if ((tid & 31) == 0) sred[tid >> 5] = cnt;
        __syncthreads();
        if (tid == 0) {
            int s = 0;
#pragma unroll
            for (int i = 0; i < 8; i++) s += sred[i];
            g_len[b] = s;
        }
    }
}

// ---------------- K1: input projection  xp = leaky(x @ Wip + bip) -----------
__global__ void __launch_bounds__(256) k_inproj(const float* __restrict__ x,
                                                const float* __restrict__ Wip,
                                                const float* __restrict__ bip) {
    __shared__ __align__(16) float sA[16][64];
    __shared__ __align__(16) float sB[16][64];
    const int tid = threadIdx.x;
    const int r0 = blockIdx.x * 64, c0 = blockIdx.y * 64;
    const int tx = tid & 15, ty = tid >> 4;
    const int am = tid >> 2, ak = (tid & 3) * 4;
    const int bk = tid >> 4, bc = (tid & 15) * 4;
    float acc[4][4] = {};
    for (int k0 = 0; k0 < NOBS; k0 += 16) {
        int r = r0 + am;
        int t = r >> 9;           // r / NB
        int b = r & (NB - 1);
        float4 av = *reinterpret_cast<const float4*>(&x[((size_t)b * NT + t) * NOBS + k0 + ak]);
        sA[ak + 0][am] = av.x; sA[ak + 1][am] = av.y;
        sA[ak + 2][am] = av.z; sA[ak + 3][am] = av.w;
        float4 bv = *reinterpret_cast<const float4*>(&Wip[(size_t)(k0 + bk) * NH + c0 + bc]);
        *reinterpret_cast<float4*>(&sB[bk][bc]) = bv;
        __syncthreads();
#pragma unroll
        for (int kk = 0; kk < 16; kk++) {
            float4 a4 = *reinterpret_cast<const float4*>(&sA[kk][ty * 4]);
            float4 b4 = *reinterpret_cast<const float4*>(&sB[kk][tx * 4]);
            float ar[4] = {a4.x, a4.y, a4.z, a4.w};
            float br[4] = {b4.x, b4.y, b4.z, b4.w};
#pragma unroll
            for (int i = 0; i < 4; i++)
#pragma unroll
                for (int jj = 0; jj < 4; jj++)
                    acc[i][jj] += ar[i] * br[jj];
        }
        __syncthreads();
    }
#pragma unroll
    for (int i = 0; i < 4; i++) {
        int r = r0 + ty * 4 + i;
        float4 v;
        float z0 = acc[i][0] + bip[c0 + tx * 4 + 0];
        float z1 = acc[i][1] + bip[c0 + tx * 4 + 1];
        float z2 = acc[i][2] + bip[c0 + tx * 4 + 2];
        float z3 = acc[i][3] + bip[c0 + tx * 4 + 3];
        v.x = z0 > 0.0f ? z0 : 0.01f * z0;
        v.y = z1 > 0.0f ? z1 : 0.01f * z1;
        v.z = z2 > 0.0f ? z2 : 0.01f * z2;
        v.w = z3 > 0.0f ? z3 : 0.01f * z3;
        *reinterpret_cast<float4*>(&g_xp[(size_t)r * NH + c0 + tx * 4]) = v;
    }
}

// ---------------- K2: gates_x = xp @ Wi_e_r + b_e_r  (f32x2 micro) ----------
// Grid is (col-tile, row-tile): the 16 col-tiles of one row-tile launch
// adjacently so the xp A-tile is DRAM-read once and L2-shared 15x.
__global__ void __launch_bounds__(256) k_gatesx(const float* __restrict__ b_e) {
    __shared__ __align__(16) float sAd[16][128];
    __shared__ __align__(16) float sB[16][64];
    const int tid = threadIdx.x;
    const size_t r0 = (size_t)blockIdx.y * 64;
    const int c0 = blockIdx.x * 64;
    const int tx = tid & 15, ty = tid >> 4;
    const int am = tid >> 2, ak = (tid & 3) * 4;
    const int bk = tid >> 4, bc = (tid & 15) * 4;
    F2U acc[4][2];
#pragma unroll
    for (int i = 0; i < 4; i++) { acc[i][0].u = 0ull; acc[i][1].u = 0ull; }
    for (int k0 = 0; k0 < NH; k0 += 16) {
        float4 av = *reinterpret_cast<const float4*>(&g_xp[(r0 + am) * NH + k0 + ak]);
        sAd[ak + 0][2 * am] = av.x; sAd[ak + 0][2 * am + 1] = av.x;
        sAd[ak + 1][2 * am] = av.y; sAd[ak + 1][2 * am + 1] = av.y;
        sAd[ak + 2][2 * am] = av.z; sAd[ak + 2][2 * am + 1] = av.z;
        sAd[ak + 3][2 * am] = av.w; sAd[ak + 3][2 * am + 1] = av.w;
        float4 bv = *reinterpret_cast<const float4*>(&g_Wr_ie[(size_t)(k0 + bk) * NG + c0 + bc]);
        *reinterpret_cast<float4*>(&sB[bk][bc]) = bv;
        __syncthreads();
#pragma unroll
        for (int kk = 0; kk < 16; kk++) {
            ulonglong2 a01 = *reinterpret_cast<const ulonglong2*>(&sAd[kk][ty * 8]);
            ulonglong2 a23 = *reinterpret_cast<const ulonglong2*>(&sAd[kk][ty * 8 + 4]);
            ulonglong2 bb  = *reinterpret_cast<const ulonglong2*>(&sB[kk][tx * 4]);
            fma2(acc[0][0].u, a01.x, bb.x); fma2(acc[0][1].u, a01.x, bb.y);
            fma2(acc[1][0].u, a01.y, bb.x); fma2(acc[1][1].u, a01.y, bb.y);
            fma2(acc[2][0].u, a23.x, bb.x); fma2(acc[2][1].u, a23.x, bb.y);
            fma2(acc[3][0].u, a23.y, bb.x); fma2(acc[3][1].u, a23.y, bb.y);
        }
        __syncthreads();
    }
    const int j = (c0 >> 2) + tx;
    const float bi_ = b_e[j], bf_ = b_e[NH + j], bg_ = b_e[2 * NH + j], bo_ = b_e[3 * NH + j];
#pragma unroll
    for (int i = 0; i < 4; i++) {
        size_t r = r0 + ty * 4 + i;
        float4 v = make_float4(acc[i][0].f[0] + bi_, acc[i][0].f[1] + bf_,
                               acc[i][1].f[0] + bg_, acc[i][1].f[1] + bo_);
        *reinterpret_cast<float4*>(&g_gx[r * NG + c0 + tx * 4]) = v;
    }
}

// ---------------- persistent scan (encoder / decoder) -----------------------
// One launch runs all steps; the 16 blocks sharing a batch tile sync through
// an atomic-free flag barrier (release-store own slot, 16 parallel acquire
// polls). SPLIT-K: 512 threads, warps 0-7 k in [0,128), warps 8-15 k in
// [128,256) for the SAME 64x64 tile. The h tile is staged DUPLICATED into
// SMEM ([k][2*row], one __syncthreads), so the GEMM inner loop is 3 LDS.128 +
// 8 FFMA2 per k with ZERO register-dup movs -> FMA pipe is the only limiter.
// Upper half publishes partials via SMEM; lower half reduces, applies gates,
// owns cell/hidden state in registers. Decoder fuses recon[t-1] = h@Wop + bop
// (split-k too) and runs a 513th pseudo-step for recon[T-1].
template <bool ENC>
__global__ void __launch_bounds__(512, 1) k_scan(unsigned ebase,
                                                 const float* __restrict__ Wop,
                                                 const float* __restrict__ bop,
                                                 float* __restrict__ out) {
    extern __shared__ float sm[];
    float* sW  = sm;                  // [256 k][64 gate-cols]   (64 KB, resident)
    float* sAd = sm + NH * 64;        // [256 k][128 = 2*row]    (128 KB, restaged per step)
    float* sP  = sAd + NH * 128;      // [256 k][4]              Wop tile (decoder only)
    float* sR  = sP + NH * 4;         // [16][256] partial-sum reduction
    float* sRp = sR + 16 * 256;       // [256] partial pred reduction

    const int tid = threadIdx.x;
    const int sub = tid & 255;                   // position within half
    const int kb  = (tid >> 8) * 128;            // k-range base for this half
    const int gid = blockIdx.x & 7;
    const int b0 = gid * 64;
    const int by = blockIdx.x >> 3;
    const int c0 = by * 64;
    const int tx = sub & 15, ty = sub >> 4;
    const int j  = (c0 >> 2) + tx;
    const int pr = sub >> 2, pc = sub & 3;
    const int sr  = tid & 63;                    // staging: row
    const int sk0 = (tid >> 6) * 32;             // staging: k-chunk base (8 chunks of 32)

    // preload weight tile (once for all steps)
    const float* __restrict__ Wg = ENC ? g_Wr_he : g_Wr_d;
    for (int q = tid; q < NH * 16; q += 512) {
        int k = q >> 4, cc = (q & 15) * 4;
        *reinterpret_cast<float4*>(&sW[k * 64 + cc]) =
            *reinterpret_cast<const float4*>(&Wg[(size_t)k * NG + c0 + cc]);
    }
    float bopv = 0.0f;
    float4 bv = make_float4(0.f, 0.f, 0.f, 0.f);
    if (!ENC) {
        for (int q = tid; q < NH * 4; q += 512)
            sP[q] = Wop[(q >> 2) * NOBS + by * 4 + (q & 3)];
        bv = *reinterpret_cast<const float4*>(&g_br_d[c0 + tx * 4]);
        bopv = bop[by * 4 + pc];
    }

    float rc[4], rh[4];
    int rlen[4];
#pragma unroll
    for (int i = 0; i < 4; i++) {
        const int b = b0 + ty * 4 + i;
        if (ENC) {
            rc[i] = 0.0f; rh[i] = 0.0f; rlen[i] = g_len[b];
            if (tid < 256) g_h[0][b * NH + j] = 0.0f;   // zero initial hidden
        } else {
            float v = g_h[0][b * NH + j];               // ctx from k_latctx
            rc[i] = v; rh[i] = v; rlen[i] = 0;
        }
    }
    __syncthreads();                                // sW/sP ready
    if (ENC) flag_barrier(gid, by, ebase + 1);      // zero-init visible in group

    // gx prefetch for step 0 (lower half only)
    float4 gv[4];
    if (ENC && tid < 256) {
#pragma unroll
        for (int i = 0; i < 4; i++)
            gv[i] = *reinterpret_cast<const float4*>(
                &g_gx[(size_t)(b0 + ty * 4 + i) * NG + c0 + tx * 4]);
    }

    const int TEND = ENC ? NT : NT + 1;
    for (int t = 0; t < TEND; t++) {
        const float* __restrict__ h_in = g_h[t & 1];
        float* __restrict__ h_out = g_h[(t & 1) ^ 1];

        // ---- stage h tile DUPLICATED: h_in[b0+sr][k] -> sAd[k][2*sr],[2*sr+1]
        {
            float4 tmp[8];
#pragma unroll
            for (int i = 0; i < 8; i++)
                tmp[i] = *reinterpret_cast<const float4*>(
                    &h_in[(size_t)(b0 + sr) * NH + sk0 + 4 * i]);
#pragma unroll
            for (int i = 0; i < 8; i++) {
                *reinterpret_cast<float2*>(&sAd[(sk0 + 4 * i + 0) * 128 + 2 * sr]) =
                    make_float2(tmp[i].x, tmp[i].x);
                *reinterpret_cast<float2*>(&sAd[(sk0 + 4 * i + 1) * 128 + 2 * sr]) =
                    make_float2(tmp[i].y, tmp[i].y);
                *reinterpret_cast<float2*>(&sAd[(sk0 + 4 * i + 2) * 128 + 2 * sr]) =
                    make_float2(tmp[i].z, tmp[i].z);
                *reinterpret_cast<float2*>(&sAd[(sk0 + 4 * i + 3) * 128 + 2 * sr]) =
                    make_float2(tmp[i].w, tmp[i].w);
            }
        }
        __syncthreads();

        F2U acc[4][2];
#pragma unroll
        for (int i = 0; i < 4; i++) { acc[i][0].u = 0ull; acc[i][1].u = 0ull; }
        float accp = 0.0f;

        // ---- split-k GEMM: k in [kb, kb+128), 3 LDS.128 + 8 FFMA2 per k ----
        ulonglong2 a01 = *reinterpret_cast<const ulonglong2*>(&sAd[kb * 128 + 2 * (ty * 4)]);
        ulonglong2 a23 = *reinterpret_cast<const ulonglong2*>(&sAd[kb * 128 + 2 * (ty * 4) + 4]);
        ulonglong2 b_cur = *reinterpret_cast<const ulonglong2*>(&sW[kb * 64 + tx * 4]);
        float p_cur = 0.0f, w_cur = 0.0f;
        if (!ENC) { p_cur = sAd[kb * 128 + 2 * pr]; w_cur = sP[kb * 4 + pc]; }
#pragma unroll 8
        for (int k = kb; k < kb + 127; k++) {
            ulonglong2 a01n = *reinterpret_cast<const ulonglong2*>(&sAd[(k + 1) * 128 + 2 * (ty * 4)]);
            ulonglong2 a23n = *reinterpret_cast<const ulonglong2*>(&sAd[(k + 1) * 128 + 2 * (ty * 4) + 4]);
            ulonglong2 b_nxt = *reinterpret_cast<const ulonglong2*>(&sW[(k + 1) * 64 + tx * 4]);
            float p_nxt = 0.0f, w_nxt = 0.0f;
            if (!ENC) { p_nxt = sAd[(k + 1) * 128 + 2 * pr]; w_nxt = sP[(k + 1) * 4 + pc]; }
            fma2(acc[0][0].u, a01.x, b_cur.x); fma2(acc[0][1].u, a01.x, b_cur.y);
            fma2(acc[1][0].u, a01.y, b_cur.x); fma2(acc[1][1].u, a01.y, b_cur.y);
            fma2(acc[2][0].u, a23.x, b_cur.x); fma2(acc[2][1].u, a23.x, b_cur.y);
            fma2(acc[3][0].u, a23.y, b_cur.x); fma2(acc[3][1].u, a23.y, b_cur.y);
            if (!ENC) accp = fmaf(p_cur, w_cur, accp);
            a01 = a01n; a23 = a23n; b_cur = b_nxt; p_cur = p_nxt; w_cur = w_nxt;
        }
        {   // final k of this half (already in registers)
            fma2(acc[0][0].u, a01.x, b_cur.x); fma2(acc[0][1].u, a01.x, b_cur.y);
            fma2(acc[1][0].u, a01.y, b_cur.x); fma2(acc[1][1].u, a01.y, b_cur.y);
            fma2(acc[2][0].u, a23.x, b_cur.x); fma2(acc[2][1].u, a23.x, b_cur.y);
            fma2(acc[3][0].u, a23.y, b_cur.x); fma2(acc[3][1].u, a23.y, b_cur.y);
            if (!ENC) accp = fmaf(p_cur, w_cur, accp);
        }

        // ---- cross-half reduction: upper half publishes partials ----
        if (tid >= 256) {
#pragma unroll
            for (int i = 0; i < 4; i++) {
                sR[(i * 4 + 0) * 256 + sub] = acc[i][0].f[0];
                sR[(i * 4 + 1) * 256 + sub] = acc[i][0].f[1];
                sR[(i * 4 + 2) * 256 + sub] = acc[i][1].f[0];
                sR[(i * 4 + 3) * 256 + sub] = acc[i][1].f[1];
            }
            if (!ENC) sRp[sub] = accp;
        }
        __syncthreads();

        if (tid < 256 && (ENC || t < NT)) {
#pragma unroll
            for (int i = 0; i < 4; i++) {
                const int b = b0 + ty * 4 + i;
                float zi = acc[i][0].f[0] + sR[(i * 4 + 0) * 256 + sub];
                float zf = acc[i][0].f[1] + sR[(i * 4 + 1) * 256 + sub];
                float zg = acc[i][1].f[0] + sR[(i * 4 + 2) * 256 + sub];
                float zo = acc[i][1].f[1] + sR[(i * 4 + 3) * 256 + sub];
                if (ENC) { zi += gv[i].x; zf += gv[i].y; zg += gv[i].z; zo += gv[i].w; }
                else     { zi += bv.x;    zf += bv.y;    zg += bv.z;    zo += bv.w; }
                float ig = fsig(zi), fg = fsig(zf), gg = ftanh(zg), og = fsig(zo);
                float nc = fg * rc[i] + ig * gg;
                float nh = og * ftanh(nc);
                if (ENC) {
                    bool m = (t < rlen[i]);                 // prefix mask
                    rc[i] = m ? nc : rc[i];
                    rh[i] = m ? nh : rh[i];
                } else {
                    rc[i] = nc; rh[i] = nh;
                }
                h_out[b * NH + j] = rh[i];
            }
        }
        if (!ENC && tid < 256 && t >= 1)
            out[((size_t)(b0 + pr) * NT + (t - 1)) * NOBS + by * 4 + pc] =
                accp + sRp[sub] + bopv;

        // prefetch gx for step t+1 (latency hidden behind the barrier wait)
        if (ENC && tid < 256 && t + 1 < NT) {
#pragma unroll
            for (int i = 0; i < 4; i++)
                gv[i] = *reinterpret_cast<const float4*>(
                    &g_gx[(size_t)(t + 1) * NB * NG + (size_t)(b0 + ty * 4 + i) * NG + c0 + tx * 4]);
        }

        if (t + 1 < TEND)
            flag_barrier(gid, by, ebase + (ENC ? (unsigned)(t + 2) : (unsigned)(t + 1)));
    }
}

// ---------------- latent + context (fused) -----------------------------------
__global__ void k_latctx(const float* __restrict__ Wlp, const float* __restrict__ blp,
                         const float* __restrict__ Wle, const float* __restrict__ ble,
                         float* __restrict__ out) {
    __shared__ float slat[NLAT];
    const int b = blockIdx.x, tid = threadIdx.x;
    const int l = tid >> 4, sub = tid & 15;
    const float* h = g_h[0];                 // final encoder h (512 steps -> buf 0)
    float s = 0.0f;
    for (int k = sub; k < NH; k += 16) s += h[b * NH + k] * Wlp[k * NLAT + l];
#pragma unroll
    for (int off = 8; off; off >>= 1) s += __shfl_xor_sync(0xffffffffu, s, off);
    if (sub == 0) {
        float v = s + blp[l];
        slat[l] = v;
        out[(size_t)NB * NT * NOBS + (size_t)b * NLAT + l] = v;
    }
    __syncthreads();
    float s2 = ble[tid];
#pragma unroll
    for (int l2 = 0; l2 < NLAT; l2++) s2 += slat[l2] * Wle[l2 * NH + tid];
    g_h[0][b * NH + tid] = s2 > 0.0f ? s2 : 0.01f * s2;   // ctx -> initial (c,h)
}

// ---------------- driver -----------------------------------------------------
extern "C" void kernel_launch(void* const* d_in, const int* in_sizes, int n_in,
                              void* d_out, int out_size) {
    (void)in_sizes; (void)n_in; (void)out_size;
    const float* x    = (const float*)d_in[0];
    const void*  mask = d_in[1];
    const float* Wip  = (const float*)d_in[2];
    const float* bip  = (const float*)d_in[3];
    const float* Wi_e = (const float*)d_in[4];
    const float* Wh_e = (const float*)d_in[5];
    const float* b_e  = (const float*)d_in[6];
    const float* Wlp  = (const float*)d_in[7];
    const float* blp  = (const float*)d_in[8];
    const float* Wle  = (const float*)d_in[9];
    const float* ble  = (const float*)d_in[10];
    const float* Wi_d = (const float*)d_in[11];
    const float* Wh_d = (const float*)d_in[12];
    const float* b_d  = (const float*)d_in[13];
    const float* Wop  = (const float*)d_in[14];
    const float* bop  = (const float*)d_in[15];
    float* out = (float*)d_out;

    // smem: sW 64K + sAd 128K + sP 4K + sR 16K + sRp 1K = 213 KB
    const size_t smem = (size_t)(NH * 64 + NH * 128 + NH * 4 + 16 * 256 + 256) * sizeof(float);
    cudaFuncSetAttribute(k_scan<true>,  cudaFuncAttributeMaxDynamicSharedMemorySize, (int)smem);
    cudaFuncSetAttribute(k_scan<false>, cudaFuncAttributeMaxDynamicSharedMemorySize, (int)smem);

    // 6 graph nodes total
    k_setup<<<1024, 256>>>(mask, Wi_e, Wh_e, Wi_d, Wh_d, b_d);
    k_inproj<<<dim3(NB * NT / 64, NH / 64), 256>>>(x, Wip, bip);
    k_gatesx<<<dim3(NG / 64, NB * NT / 64), 256>>>(b_e);
    k_scan<true><<<NBLK, 512, smem>>>(0u, nullptr, nullptr, nullptr);
    k_latctx<<<NB, 256>>>(Wlp, blp, Wle, ble, out);
    k_scan<false><<<NBLK, 512, smem>>>(512u, Wop, bop, out);
}

// round 12
// speedup vs baseline: 1.2028x; 1.2028x over previous
#include <cuda_runtime.h>

// Problem dimensions
static constexpr int NB = 512;   // batch
static constexpr int NT = 512;   // time
static constexpr int NOBS = 64;  // obs dim
static constexpr int NH = 256;   // hidden
static constexpr int NG = 1024;  // 4*H
static constexpr int NLAT = 16;  // latent
static constexpr int NBLK = 128; // persistent grid (8 batch-tiles x 16 col-tiles)

// ---------------- scratch (device globals; no allocation allowed) ----------
__device__ float g_xp[(size_t)NT * NB * NH];   // [t*NB+b][h] = leaky(x@Wip+bip)
__device__ float g_gx[(size_t)NT * NB * NG];   // [t*NB+b][4j+g] = xp@Wi_e + b_e
__device__ float g_Wr_ie[NH * NG];             // Wi_e reordered: [k][4j+g]
__device__ float g_Wr_he[NH * NG];             // Wh_e reordered
__device__ float g_Wr_d[NH * NG];              // (Wi_d + Wh_d) reordered
__device__ float g_br_d[NG];                   // b_d reordered
__device__ float g_h[2][NB * NH];              // ping-pong hidden state
__device__ int   g_len[NB];                    // per-row valid length (prefix mask)
__device__ unsigned g_flag[8][16 * 32];        // per-(group,block) step flags, 128B stride

// ---------------- helpers ---------------------------------------------------
union F2U { unsigned long long u; float f[2]; };

__device__ __forceinline__ void fma2(unsigned long long& d, unsigned long long a,
                                     unsigned long long b) {
    asm("fma.rn.f32x2 %0, %1, %2, %0;" : "+l"(d) : "l"(a), "l"(b));
}

// duplicate a scalar float into both lanes of a packed f32x2 register pair
__device__ __forceinline__ unsigned long long dupr(float x) {
    unsigned long long r;
    asm("mov.b64 %0, {%1, %1};" : "=l"(r) : "f"(x));
    return r;
}

__device__ __forceinline__ float fsig(float x) {
    return __fdividef(1.0f, 1.0f + __expf(-x));
}
__device__ __forceinline__ float ftanh(float x) {
    return 1.0f - __fdividef(2.0f, __expf(2.0f * x) + 1.0f);
}

// Atomic-free group barrier: each of the 16 blocks sharing batch-tile gid
// release-stores the step target into its own slot (no MEMBAR, no atomics);
// EVERY warp polls the 16 slots in parallel (lanes 0-15, ld.acquire) so warps
// wake independently and start their staging loads immediately. Acquire +
// __syncwarp gives every lane visibility of all peers' h writes.
__device__ __forceinline__ void flag_barrier(int gid, int myslot, unsigned target) {
    __syncthreads();
    if (threadIdx.x == 0)
        asm volatile("st.release.gpu.global.b32 [%0], %1;"
                     :: "l"(&g_flag[gid][myslot * 32]), "r"(target) : "memory");
    const int lane = threadIdx.x & 31;
    if (lane < 16) {
        unsigned cur;
        do {
            asm volatile("ld.acquire.gpu.global.b32 %0, [%1];"
                         : "=r"(cur) : "l"(&g_flag[gid][lane * 32]) : "memory");
        } while ((int)(cur - target) < 0);
    }
    __syncwarp();
}

// ---------------- setup: weight reorder + mask lengths + flag reset ----------
__global__ void k_setup(const void* __restrict__ mask,
                        const float* __restrict__ Wi_e, const float* __restrict__ Wh_e,
                        const float* __restrict__ Wi_d, const float* __restrict__ Wh_d,
                        const float* __restrict__ b_d) {
    const int idx = blockIdx.x * 256 + threadIdx.x;   // grid 1024 x 256 = NH*NG
    {
        int k = idx >> 10, c = idx & 1023;
        int g = c & 3, j = c >> 2;
        int src = k * NG + g * NH + j;
        g_Wr_ie[idx] = Wi_e[src];
        g_Wr_he[idx] = Wh_e[src];
        g_Wr_d[idx]  = Wi_d[src] + Wh_d[src];   // decoder input == hidden -> fold
    }
    if (idx < NG) {
        int g = idx & 3, j = idx >> 2;
        g_br_d[idx] = b_d[g * NH + j];
    }
    if (idx < 8 * 16 * 32) ((unsigned*)g_flag)[idx] = 0u;
    // lengths: blocks [0, NB) each count one mask row
    if (blockIdx.x < NB) {
        const int b = blockIdx.x, tid = threadIdx.x;
        // mask[0][0] is guaranteed true; int32 read of a u8-bool row front is 0x01010101
        const bool u8 = (((const int*)mask)[0] != 1);
        int cnt = 0;
        for (int t = tid; t < NT; t += 256)
            cnt += u8 ? (((const unsigned char*)mask)[(size_t)b * NT + t] != 0)
                      : (((const int*)mask)[(size_t)b * NT + t] != 0);
#pragma unroll
        for (int off = 16; off; off >>= 1) cnt += __shfl_xor_sync(0xffffffffu, cnt, off);
        __shared__ int sred[8];
        if ((tid & 31) == 0) sred[tid >> 5] = cnt;
        __syncthreads();
        if (tid == 0) {
            int s = 0;
#pragma unroll
            for (int i = 0; i < 8; i++) s += sred[i];
            g_len[b] = s;
        }
    }
}

// ---------------- K1: input projection  xp = leaky(x @ Wip + bip) -----------
__global__ void __launch_bounds__(256) k_inproj(const float* __restrict__ x,
                                                const float* __restrict__ Wip,
                                                const float* __restrict__ bip) {
    __shared__ __align__(16) float sA[16][64];
    __shared__ __align__(16) float sB[16][64];
    const int tid = threadIdx.x;
    const int r0 = blockIdx.x * 64, c0 = blockIdx.y * 64;
    const int tx = tid & 15, ty = tid >> 4;
    const int am = tid >> 2, ak = (tid & 3) * 4;
    const int bk = tid >> 4, bc = (tid & 15) * 4;
    float acc[4][4] = {};
    for (int k0 = 0; k0 < NOBS; k0 += 16) {
        int r = r0 + am;
        int t = r >> 9;           // r / NB
        int b = r & (NB - 1);
        float4 av = *reinterpret_cast<const float4*>(&x[((size_t)b * NT + t) * NOBS + k0 + ak]);
        sA[ak + 0][am] = av.x; sA[ak + 1][am] = av.y;
        sA[ak + 2][am] = av.z; sA[ak + 3][am] = av.w;
        float4 bv = *reinterpret_cast<const float4*>(&Wip[(size_t)(k0 + bk) * NH + c0 + bc]);
        *reinterpret_cast<float4*>(&sB[bk][bc]) = bv;
        __syncthreads();
#pragma unroll
        for (int kk = 0; kk < 16; kk++) {
            float4 a4 = *reinterpret_cast<const float4*>(&sA[kk][ty * 4]);
            float4 b4 = *reinterpret_cast<const float4*>(&sB[kk][tx * 4]);
            float ar[4] = {a4.x, a4.y, a4.z, a4.w};
            float br[4] = {b4.x, b4.y, b4.z, b4.w};
#pragma unroll
            for (int i = 0; i < 4; i++)
#pragma unroll
                for (int jj = 0; jj < 4; jj++)
                    acc[i][jj] += ar[i] * br[jj];
        }
        __syncthreads();
    }
#pragma unroll
    for (int i = 0; i < 4; i++) {
        int r = r0 + ty * 4 + i;
        float4 v;
        float z0 = acc[i][0] + bip[c0 + tx * 4 + 0];
        float z1 = acc[i][1] + bip[c0 + tx * 4 + 1];
        float z2 = acc[i][2] + bip[c0 + tx * 4 + 2];
        float z3 = acc[i][3] + bip[c0 + tx * 4 + 3];
        v.x = z0 > 0.0f ? z0 : 0.01f * z0;
        v.y = z1 > 0.0f ? z1 : 0.01f * z1;
        v.z = z2 > 0.0f ? z2 : 0.01f * z2;
        v.w = z3 > 0.0f ? z3 : 0.01f * z3;
        *reinterpret_cast<float4*>(&g_xp[(size_t)r * NH + c0 + tx * 4]) = v;
    }
}

// ---------------- K2: gates_x = xp @ Wi_e_r + b_e_r ---------------------------
// 64x128 tile, 4x8 micro (16 fma2 per k per thread -> FMA-bound), un-duplicated
// A with register dup via mov.b64. Grid (col-tile, row-tile) so the 8 col-tiles
// of one row-tile share the xp A-tile through L2.
__global__ void __launch_bounds__(256) k_gatesx(const float* __restrict__ b_e) {
    __shared__ __align__(16) float sA[16 * 64];    // [k][row], un-duplicated
    __shared__ __align__(16) float sB[16 * 128];
    const int tid = threadIdx.x;
    const size_t r0 = (size_t)blockIdx.y * 64;
    const int c0 = blockIdx.x * 128;
    const int tx = tid & 15, ty = tid >> 4;        // tx: 16 col-groups x 8, ty: 16 row-groups x 4
    const int am = tid >> 2, ak = (tid & 3) * 4;
    const int bk = tid >> 4, bc = (tid & 15) * 8;
    F2U acc[4][4];
#pragma unroll
    for (int i = 0; i < 4; i++)
#pragma unroll
        for (int q = 0; q < 4; q++) acc[i][q].u = 0ull;
    for (int k0 = 0; k0 < NH; k0 += 16) {
        float4 av = *reinterpret_cast<const float4*>(&g_xp[(r0 + am) * NH + k0 + ak]);
        sA[(ak + 0) * 64 + am] = av.x;
        sA[(ak + 1) * 64 + am] = av.y;
        sA[(ak + 2) * 64 + am] = av.z;
        sA[(ak + 3) * 64 + am] = av.w;
        *reinterpret_cast<float4*>(&sB[bk * 128 + bc]) =
            *reinterpret_cast<const float4*>(&g_Wr_ie[(size_t)(k0 + bk) * NG + c0 + bc]);
        *reinterpret_cast<float4*>(&sB[bk * 128 + bc + 4]) =
            *reinterpret_cast<const float4*>(&g_Wr_ie[(size_t)(k0 + bk) * NG + c0 + bc + 4]);
        __syncthreads();
#pragma unroll
        for (int kk = 0; kk < 16; kk++) {
            float4 a4 = *reinterpret_cast<const float4*>(&sA[kk * 64 + ty * 4]);
            ulonglong2 b0 = *reinterpret_cast<const ulonglong2*>(&sB[kk * 128 + tx * 8]);
            ulonglong2 b1 = *reinterpret_cast<const ulonglong2*>(&sB[kk * 128 + tx * 8 + 4]);
            unsigned long long a0 = dupr(a4.x), a1 = dupr(a4.y);
            unsigned long long a2 = dupr(a4.z), a3 = dupr(a4.w);
            fma2(acc[0][0].u, a0, b0.x); fma2(acc[0][1].u, a0, b0.y);
            fma2(acc[0][2].u, a0, b1.x); fma2(acc[0][3].u, a0, b1.y);
            fma2(acc[1][0].u, a1, b0.x); fma2(acc[1][1].u, a1, b0.y);
            fma2(acc[1][2].u, a1, b1.x); fma2(acc[1][3].u, a1, b1.y);
            fma2(acc[2][0].u, a2, b0.x); fma2(acc[2][1].u, a2, b0.y);
            fma2(acc[2][2].u, a2, b1.x); fma2(acc[2][3].u, a2, b1.y);
            fma2(acc[3][0].u, a3, b0.x); fma2(acc[3][1].u, a3, b0.y);
            fma2(acc[3][2].u, a3, b1.x); fma2(acc[3][3].u, a3, b1.y);
        }
        __syncthreads();
    }
    const int j0 = (c0 >> 2) + tx * 2, j1 = j0 + 1;
    const float bi0 = b_e[j0], bf0 = b_e[NH + j0], bg0 = b_e[2 * NH + j0], bo0 = b_e[3 * NH + j0];
    const float bi1 = b_e[j1], bf1 = b_e[NH + j1], bg1 = b_e[2 * NH + j1], bo1 = b_e[3 * NH + j1];
#pragma unroll
    for (int i = 0; i < 4; i++) {
        size_t r = r0 + ty * 4 + i;
        float4 v0 = make_float4(acc[i][0].f[0] + bi0, acc[i][0].f[1] + bf0,
                                acc[i][1].f[0] + bg0, acc[i][1].f[1] + bo0);
        float4 v1 = make_float4(acc[i][2].f[0] + bi1, acc[i][2].f[1] + bf1,
                                acc[i][3].f[0] + bg1, acc[i][3].f[1] + bo1);
        *reinterpret_cast<float4*>(&g_gx[r * NG + c0 + tx * 8])     = v0;
        *reinterpret_cast<float4*>(&g_gx[r * NG + c0 + tx * 8 + 4]) = v1;
    }
}

// ---------------- persistent scan (encoder / decoder) -----------------------
// One launch runs all steps; the 16 blocks sharing a batch tile sync through
// the atomic-free flag barrier. SPLIT-K: 512 threads, warps 0-7 k in [0,128),
// warps 8-15 k in [128,256) for the SAME 64x64 tile (weight-row LDS at the
// 8-warp level, 4 warps/SMSP hide LDS latency). Un-duplicated A, register dup.
// Upper half publishes partials via SMEM; lower half reduces, applies gates,
// owns cell/hidden state in registers. Decoder fuses recon[t-1] = h@Wop + bop
// (split-k too) and runs a 513th pseudo-step for recon[T-1].
template <bool ENC>
__global__ void __launch_bounds__(512, 1) k_scan(unsigned ebase,
                                                 const float* __restrict__ Wop,
                                                 const float* __restrict__ bop,
                                                 float* __restrict__ out) {
    extern __shared__ float sm[];
    float* sW  = sm;                  // [256 k][64 gate-cols]  (64 KB, resident)
    float* sA  = sm + NH * 64;        // [256 k][64 rows]       (64 KB, restaged per step)
    float* sP  = sA + NH * 64;        // [256 k][4]             Wop tile (decoder only)
    float* sR  = sP + NH * 4;         // [16][256] partial-sum reduction
    float* sRp = sR + 16 * 256;       // [256] partial pred reduction

    const int tid = threadIdx.x;
    const int sub = tid & 255;                   // position within half
    const int kb  = (tid >> 8) * 128;            // k-range base for this half
    const int gid = blockIdx.x & 7;
    const int b0 = gid * 64;
    const int by = blockIdx.x >> 3;
    const int c0 = by * 64;
    const int tx = sub & 15, ty = sub >> 4;
    const int j  = (c0 >> 2) + tx;
    const int pr = sub >> 2, pc = sub & 3;
    const int sr  = tid & 63;                    // staging: row
    const int sk0 = (tid >> 6) * 32;             // staging: k-chunk base (8 chunks of 32)

    // preload weight tile (once for all steps)
    const float* __restrict__ Wg = ENC ? g_Wr_he : g_Wr_d;
    for (int q = tid; q < NH * 16; q += 512) {
        int k = q >> 4, cc = (q & 15) * 4;
        *reinterpret_cast<float4*>(&sW[k * 64 + cc]) =
            *reinterpret_cast<const float4*>(&Wg[(size_t)k * NG + c0 + cc]);
    }
    float bopv = 0.0f;
    float4 bv = make_float4(0.f, 0.f, 0.f, 0.f);
    if (!ENC) {
        for (int q = tid; q < NH * 4; q += 512)
            sP[q] = Wop[(q >> 2) * NOBS + by * 4 + (q & 3)];
        bv = *reinterpret_cast<const float4*>(&g_br_d[c0 + tx * 4]);
        bopv = bop[by * 4 + pc];
    }

    float rc[4], rh[4];
    int rlen[4];
#pragma unroll
    for (int i = 0; i < 4; i++) {
        const int b = b0 + ty * 4 + i;
        if (ENC) {
            rc[i] = 0.0f; rh[i] = 0.0f; rlen[i] = g_len[b];
            if (tid < 256) g_h[0][b * NH + j] = 0.0f;   // zero initial hidden
        } else {
            float v = g_h[0][b * NH + j];               // ctx from k_latctx
            rc[i] = v; rh[i] = v; rlen[i] = 0;
        }
    }
    __syncthreads();                                // sW/sP ready
    if (ENC) flag_barrier(gid, by, ebase + 1);      // zero-init visible in group

    // gx prefetch for step 0 (lower half only)
    float4 gv[4];
    if (ENC && tid < 256) {
#pragma unroll
        for (int i = 0; i < 4; i++)
            gv[i] = *reinterpret_cast<const float4*>(
                &g_gx[(size_t)(b0 + ty * 4 + i) * NG + c0 + tx * 4]);
    }

    const int TEND = ENC ? NT : NT + 1;
    for (int t = 0; t < TEND; t++) {
        const float* __restrict__ h_in = g_h[t & 1];
        float* __restrict__ h_out = g_h[(t & 1) ^ 1];

        // ---- stage full A tile: h_in[b0+sr][sk0..sk0+31] -> sA[k][row] ----
        {
            float4 tmp[8];
#pragma unroll
            for (int i = 0; i < 8; i++)
                tmp[i] = *reinterpret_cast<const float4*>(
                    &h_in[(size_t)(b0 + sr) * NH + sk0 + 4 * i]);
#pragma unroll
            for (int i = 0; i < 8; i++) {
                sA[(sk0 + 4 * i + 0) * 64 + sr] = tmp[i].x;
                sA[(sk0 + 4 * i + 1) * 64 + sr] = tmp[i].y;
                sA[(sk0 + 4 * i + 2) * 64 + sr] = tmp[i].z;
                sA[(sk0 + 4 * i + 3) * 64 + sr] = tmp[i].w;
            }
        }
        __syncthreads();

        F2U acc[4][2];
#pragma unroll
        for (int i = 0; i < 4; i++) { acc[i][0].u = 0ull; acc[i][1].u = 0ull; }
        float accp = 0.0f;

        // ---- split-k GEMM: this half covers k in [kb, kb+128) ----
        float4 a_cur = *reinterpret_cast<const float4*>(&sA[kb * 64 + ty * 4]);
        ulonglong2 b_cur = *reinterpret_cast<const ulonglong2*>(&sW[kb * 64 + tx * 4]);
        float p_cur = 0.0f, w_cur = 0.0f;
        if (!ENC) { p_cur = sA[kb * 64 + pr]; w_cur = sP[kb * 4 + pc]; }
#pragma unroll 8
        for (int k = kb; k < kb + 127; k++) {
            float4 a_nxt = *reinterpret_cast<const float4*>(&sA[(k + 1) * 64 + ty * 4]);
            ulonglong2 b_nxt = *reinterpret_cast<const ulonglong2*>(&sW[(k + 1) * 64 + tx * 4]);
            float p_nxt = 0.0f, w_nxt = 0.0f;
            if (!ENC) { p_nxt = sA[(k + 1) * 64 + pr]; w_nxt = sP[(k + 1) * 4 + pc]; }
            unsigned long long a0 = dupr(a_cur.x), a1 = dupr(a_cur.y);
            unsigned long long a2 = dupr(a_cur.z), a3 = dupr(a_cur.w);
            fma2(acc[0][0].u, a0, b_cur.x); fma2(acc[0][1].u, a0, b_cur.y);
            fma2(acc[1][0].u, a1, b_cur.x); fma2(acc[1][1].u, a1, b_cur.y);
            fma2(acc[2][0].u, a2, b_cur.x); fma2(acc[2][1].u, a2, b_cur.y);
            fma2(acc[3][0].u, a3, b_cur.x); fma2(acc[3][1].u, a3, b_cur.y);
            if (!ENC) accp = fmaf(p_cur, w_cur, accp);
            a_cur = a_nxt; b_cur = b_nxt; p_cur = p_nxt; w_cur = w_nxt;
        }
        {   // final k of this half (already in registers)
            unsigned long long a0 = dupr(a_cur.x), a1 = dupr(a_cur.y);
            unsigned long long a2 = dupr(a_cur.z), a3 = dupr(a_cur.w);
            fma2(acc[0][0].u, a0, b_cur.x); fma2(acc[0][1].u, a0, b_cur.y);
            fma2(acc[1][0].u, a1, b_cur.x); fma2(acc[1][1].u, a1, b_cur.y);
            fma2(acc[2][0].u, a2, b_cur.x); fma2(acc[2][1].u, a2, b_cur.y);
            fma2(acc[3][0].u, a3, b_cur.x); fma2(acc[3][1].u, a3, b_cur.y);
            if (!ENC) accp = fmaf(p_cur, w_cur, accp);
        }

        // ---- cross-half reduction: upper half publishes partials ----
        if (tid >= 256) {
#pragma unroll
            for (int i = 0; i < 4; i++) {
                sR[(i * 4 + 0) * 256 + sub] = acc[i][0].f[0];
                sR[(i * 4 + 1) * 256 + sub] = acc[i][0].f[1];
                sR[(i * 4 + 2) * 256 + sub] = acc[i][1].f[0];
                sR[(i * 4 + 3) * 256 + sub] = acc[i][1].f[1];
            }
            if (!ENC) sRp[sub] = accp;
        }
        __syncthreads();

        if (tid < 256 && (ENC || t < NT)) {
#pragma unroll
            for (int i = 0; i < 4; i++) {
                const int b = b0 + ty * 4 + i;
                float zi = acc[i][0].f[0] + sR[(i * 4 + 0) * 256 + sub];
                float zf = acc[i][0].f[1] + sR[(i * 4 + 1) * 256 + sub];
                float zg = acc[i][1].f[0] + sR[(i * 4 + 2) * 256 + sub];
                float zo = acc[i][1].f[1] + sR[(i * 4 + 3) * 256 + sub];
                if (ENC) { zi += gv[i].x; zf += gv[i].y; zg += gv[i].z; zo += gv[i].w; }
                else     { zi += bv.x;    zf += bv.y;    zg += bv.z;    zo += bv.w; }
                float ig = fsig(zi), fg = fsig(zf), gg = ftanh(zg), og = fsig(zo);
                float nc = fg * rc[i] + ig * gg;
                float nh = og * ftanh(nc);
                if (ENC) {
                    bool m = (t < rlen[i]);                 // prefix mask
                    rc[i] = m ? nc : rc[i];
                    rh[i] = m ? nh : rh[i];
                } else {
                    rc[i] = nc; rh[i] = nh;
                }
                h_out[b * NH + j] = rh[i];
            }
        }
        if (!ENC && tid < 256 && t >= 1)
            out[((size_t)(b0 + pr) * NT + (t - 1)) * NOBS + by * 4 + pc] =
                accp + sRp[sub] + bopv;

        // prefetch gx for step t+1 (latency hidden behind the barrier wait)
        if (ENC && tid < 256 && t + 1 < NT) {
#pragma unroll
            for (int i = 0; i < 4; i++)
                gv[i] = *reinterpret_cast<const float4*>(
                    &g_gx[(size_t)(t + 1) * NB * NG + (size_t)(b0 + ty * 4 + i) * NG + c0 + tx * 4]);
        }

        if (t + 1 < TEND)
            flag_barrier(gid, by, ebase + (ENC ? (unsigned)(t + 2) : (unsigned)(t + 1)));
    }
}

// ---------------- latent + context (fused) -----------------------------------
__global__ void k_latctx(const float* __restrict__ Wlp, const float* __restrict__ blp,
                         const float* __restrict__ Wle, const float* __restrict__ ble,
                         float* __restrict__ out) {
    __shared__ float slat[NLAT];
    const int b = blockIdx.x, tid = threadIdx.x;
    const int l = tid >> 4, sub = tid & 15;
    const float* h = g_h[0];                 // final encoder h (512 steps -> buf 0)
    float s = 0.0f;
    for (int k = sub; k < NH; k += 16) s += h[b * NH + k] * Wlp[k * NLAT + l];
#pragma unroll
    for (int off = 8; off; off >>= 1) s += __shfl_xor_sync(0xffffffffu, s, off);
    if (sub == 0) {
        float v = s + blp[l];
        slat[l] = v;
        out[(size_t)NB * NT * NOBS + (size_t)b * NLAT + l] = v;
    }
    __syncthreads();
    float s2 = ble[tid];
#pragma unroll
    for (int l2 = 0; l2 < NLAT; l2++) s2 += slat[l2] * Wle[l2 * NH + tid];
    g_h[0][b * NH + tid] = s2 > 0.0f ? s2 : 0.01f * s2;   // ctx -> initial (c,h)
}

// ---------------- driver -----------------------------------------------------
extern "C" void kernel_launch(void* const* d_in, const int* in_sizes, int n_in,
                              void* d_out, int out_size) {
    (void)in_sizes; (void)n_in; (void)out_size;
    const float* x    = (const float*)d_in[0];
    const void*  mask = d_in[1];
    const float* Wip  = (const float*)d_in[2];
    const float* bip  = (const float*)d_in[3];
    const float* Wi_e = (const float*)d_in[4];
    const float* Wh_e = (const float*)d_in[5];
    const float* b_e  = (const float*)d_in[6];
    const float* Wlp  = (const float*)d_in[7];
    const float* blp  = (const float*)d_in[8];
    const float* Wle  = (const float*)d_in[9];
    const float* ble  = (const float*)d_in[10];
    const float* Wi_d = (const float*)d_in[11];
    const float* Wh_d = (const float*)d_in[12];
    const float* b_d  = (const float*)d_in[13];
    const float* Wop  = (const float*)d_in[14];
    const float* bop  = (const float*)d_in[15];
    float* out = (float*)d_out;

    // smem: sW 64K + sA 64K + sP 4K + sR 16K + sRp 1K = 149 KB
    const size_t smem = (size_t)(NH * 64 + NH * 64 + NH * 4 + 16 * 256 + 256) * sizeof(float);
    cudaFuncSetAttribute(k_scan<true>,  cudaFuncAttributeMaxDynamicSharedMemorySize, (int)smem);
    cudaFuncSetAttribute(k_scan<false>, cudaFuncAttributeMaxDynamicSharedMemorySize, (int)smem);

    // 6 graph nodes total
    k_setup<<<1024, 256>>>(mask, Wi_e, Wh_e, Wi_d, Wh_d, b_d);
    k_inproj<<<dim3(NB * NT / 64, NH / 64), 256>>>(x, Wip, bip);
    k_gatesx<<<dim3(NG / 128, NB * NT / 64), 256>>>(b_e);
    k_scan<true><<<NBLK, 512, smem>>>(0u, nullptr, nullptr, nullptr);
    k_latctx<<<NB, 256>>>(Wlp, blp, Wle, ble, out);
    k_scan<false><<<NBLK, 512, smem>>>(512u, Wop, bop, out);
}

// round 13
// speedup vs baseline: 1.2277x; 1.0208x over previous
#include <cuda_runtime.h>

// Problem dimensions
static constexpr int NB = 512;   // batch
static constexpr int NT = 512;   // time
static constexpr int NOBS = 64;  // obs dim
static constexpr int NH = 256;   // hidden
static constexpr int NG = 1024;  // 4*H
static constexpr int NLAT = 16;  // latent
static constexpr int NBLK = 128; // persistent grid (8 group-pairs x 16 col-tiles)

// ---------------- scratch (device globals; no allocation allowed) ----------
__device__ float g_xp[(size_t)NT * NB * NH];   // [t*NB+b][h] = leaky(x@Wip+bip)
__device__ float g_gx[(size_t)NT * NB * NG];   // [t*NB+b][4j+g] = xp@Wi_e + b_e
__device__ float g_Wr_ie[NH * NG];             // Wi_e reordered: [k][4j+g]
__device__ float g_Wr_he[NH * NG];             // Wh_e reordered
__device__ float g_Wr_d[NH * NG];              // (Wi_d + Wh_d) reordered
__device__ float g_br_d[NG];                   // b_d reordered
__device__ float g_h[2][NB * NH];              // ping-pong hidden state
__device__ int   g_len[NB];                    // per-row valid length (prefix mask)
__device__ unsigned g_flag[16][16 * 32];       // per-(group,block) step flags, 128B stride

// ---------------- helpers ---------------------------------------------------
union F2U { unsigned long long u; float f[2]; };

__device__ __forceinline__ void fma2(unsigned long long& d, unsigned long long a,
                                     unsigned long long b) {
    asm("fma.rn.f32x2 %0, %1, %2, %0;" : "+l"(d) : "l"(a), "l"(b));
}

// duplicate a scalar float into both lanes of a packed f32x2 register pair
__device__ __forceinline__ unsigned long long dupr(float x) {
    unsigned long long r;
    asm("mov.b64 %0, {%1, %1};" : "=l"(r) : "f"(x));
    return r;
}

__device__ __forceinline__ float fsig(float x) {
    return __fdividef(1.0f, 1.0f + __expf(-x));
}
__device__ __forceinline__ float ftanh(float x) {
    return 1.0f - __fdividef(2.0f, __expf(2.0f * x) + 1.0f);
}

// named barrier over the 256 threads of one job (barid 1 or 2)
__device__ __forceinline__ void barj(int barid) {
    asm volatile("bar.sync %0, 256;" :: "r"(barid) : "memory");
}

// Per-job flag barrier: syncs the 16 blocks that share group g. Each job
// release-stores the step target into its own slot; every warp of the job
// polls the 16 slots in parallel (lanes 0-15, ld.acquire), then __syncwarp.
__device__ __forceinline__ void job_flag_barrier(int barid, int g, int myslot,
                                                 unsigned target) {
    barj(barid);                                  // job's h writes all done
    if ((threadIdx.x & 255) == 0)
        asm volatile("st.release.gpu.global.b32 [%0], %1;"
                     :: "l"(&g_flag[g][myslot * 32]), "r"(target) : "memory");
    const int lane = threadIdx.x & 31;
    if (lane < 16) {
        unsigned cur;
        do {
            asm volatile("ld.acquire.gpu.global.b32 %0, [%1];"
                         : "=r"(cur) : "l"(&g_flag[g][lane * 32]) : "memory");
        } while ((int)(cur - target) < 0);
    }
    __syncwarp();
}

// ---------------- setup: weight reorder + mask lengths + flag reset ----------
__global__ void k_setup(const void* __restrict__ mask,
                        const float* __restrict__ Wi_e, const float* __restrict__ Wh_e,
                        const float* __restrict__ Wi_d, const float* __restrict__ Wh_d,
                        const float* __restrict__ b_d) {
    const int idx = blockIdx.x * 256 + threadIdx.x;   // grid 1024 x 256 = NH*NG
    {
        int k = idx >> 10, c = idx & 1023;
        int g = c & 3, j = c >> 2;
        int src = k * NG + g * NH + j;
        g_Wr_ie[idx] = Wi_e[src];
        g_Wr_he[idx] = Wh_e[src];
        g_Wr_d[idx]  = Wi_d[src] + Wh_d[src];   // decoder input == hidden -> fold
    }
    if (idx < NG) {
        int g = idx & 3, j = idx >> 2;
        g_br_d[idx] = b_d[g * NH + j];
    }
    if (idx < 16 * 16 * 32) ((unsigned*)g_flag)[idx] = 0u;
    // lengths: blocks [0, NB) each count one mask row
    if (blockIdx.x < NB) {
        const int b = blockIdx.x, tid = threadIdx.x;
        // mask[0][0] is guaranteed true; int32 read of a u8-bool row front is 0x01010101
        const bool u8 = (((const int*)mask)[0] != 1);
        int cnt = 0;
        for (int t = tid; t < NT; t += 256)
            cnt += u8 ? (((const unsigned char*)mask)[(size_t)b * NT + t] != 0)
                      : (((const int*)mask)[(size_t)b * NT + t] != 0);
#pragma unroll
        for (int off = 16; off; off >>= 1) cnt += __shfl_xor_sync(0xffffffffu, cnt, off);
        __shared__ int sred[8];
        if ((tid & 31) == 0) sred[tid >> 5] = cnt;
        __syncthreads();
        if (tid == 0) {
            int s = 0;
#pragma unroll
            for (int i = 0; i < 8; i++) s += sred[i];
            g_len[b] = s;
        }
    }
}

// ---------------- K1: input projection  xp = leaky(x @ Wip + bip) -----------
__global__ void __launch_bounds__(256) k_inproj(const float* __restrict__ x,
                                                const float* __restrict__ Wip,
                                                const float* __restrict__ bip) {
    __shared__ __align__(16) float sA[16][64];
    __shared__ __align__(16) float sB[16][64];
    const int tid = threadIdx.x;
    const int r0 = blockIdx.x * 64, c0 = blockIdx.y * 64;
    const int tx = tid & 15, ty = tid >> 4;
    const int am = tid >> 2, ak = (tid & 3) * 4;
    const int bk = tid >> 4, bc = (tid & 15) * 4;
    float acc[4][4] = {};
    for (int k0 = 0; k0 < NOBS; k0 += 16) {
        int r = r0 + am;
        int t = r >> 9;           // r / NB
        int b = r & (NB - 1);
        float4 av = *reinterpret_cast<const float4*>(&x[((size_t)b * NT + t) * NOBS + k0 + ak]);
        sA[ak + 0][am] = av.x; sA[ak + 1][am] = av.y;
        sA[ak + 2][am] = av.z; sA[ak + 3][am] = av.w;
        float4 bv = *reinterpret_cast<const float4*>(&Wip[(size_t)(k0 + bk) * NH + c0 + bc]);
        *reinterpret_cast<float4*>(&sB[bk][bc]) = bv;
        __syncthreads();
#pragma unroll
        for (int kk = 0; kk < 16; kk++) {
            float4 a4 = *reinterpret_cast<const float4*>(&sA[kk][ty * 4]);
            float4 b4 = *reinterpret_cast<const float4*>(&sB[kk][tx * 4]);
            float ar[4] = {a4.x, a4.y, a4.z, a4.w};
            float br[4] = {b4.x, b4.y, b4.z, b4.w};
#pragma unroll
            for (int i = 0; i < 4; i++)
#pragma unroll
                for (int jj = 0; jj < 4; jj++)
                    acc[i][jj] += ar[i] * br[jj];
        }
        __syncthreads();
    }
#pragma unroll
    for (int i = 0; i < 4; i++) {
        int r = r0 + ty * 4 + i;
        float4 v;
        float z0 = acc[i][0] + bip[c0 + tx * 4 + 0];
        float z1 = acc[i][1] + bip[c0 + tx * 4 + 1];
        float z2 = acc[i][2] + bip[c0 + tx * 4 + 2];
        float z3 = acc[i][3] + bip[c0 + tx * 4 + 3];
        v.x = z0 > 0.0f ? z0 : 0.01f * z0;
        v.y = z1 > 0.0f ? z1 : 0.01f * z1;
        v.z = z2 > 0.0f ? z2 : 0.01f * z2;
        v.w = z3 > 0.0f ? z3 : 0.01f * z3;
        *reinterpret_cast<float4*>(&g_xp[(size_t)r * NH + c0 + tx * 4]) = v;
    }
}

// ---------------- K2: gates_x = xp @ Wi_e_r + b_e_r ---------------------------
// 64x128 tile, 4x8 micro, un-duplicated A with register dup (R12-proven).
__global__ void __launch_bounds__(256) k_gatesx(const float* __restrict__ b_e) {
    __shared__ __align__(16) float sA[16 * 64];
    __shared__ __align__(16) float sB[16 * 128];
    const int tid = threadIdx.x;
    const size_t r0 = (size_t)blockIdx.y * 64;
    const int c0 = blockIdx.x * 128;
    const int tx = tid & 15, ty = tid >> 4;
    const int am = tid >> 2, ak = (tid & 3) * 4;
    const int bk = tid >> 4, bc = (tid & 15) * 8;
    F2U acc[4][4];
#pragma unroll
    for (int i = 0; i < 4; i++)
#pragma unroll
        for (int q = 0; q < 4; q++) acc[i][q].u = 0ull;
    for (int k0 = 0; k0 < NH; k0 += 16) {
        float4 av = *reinterpret_cast<const float4*>(&g_xp[(r0 + am) * NH + k0 + ak]);
        sA[(ak + 0) * 64 + am] = av.x;
        sA[(ak + 1) * 64 + am] = av.y;
        sA[(ak + 2) * 64 + am] = av.z;
        sA[(ak + 3) * 64 + am] = av.w;
        *reinterpret_cast<float4*>(&sB[bk * 128 + bc]) =
            *reinterpret_cast<const float4*>(&g_Wr_ie[(size_t)(k0 + bk) * NG + c0 + bc]);
        *reinterpret_cast<float4*>(&sB[bk * 128 + bc + 4]) =
            *reinterpret_cast<const float4*>(&g_Wr_ie[(size_t)(k0 + bk) * NG + c0 + bc + 4]);
        __syncthreads();
#pragma unroll
        for (int kk = 0; kk < 16; kk++) {
            float4 a4 = *reinterpret_cast<const float4*>(&sA[kk * 64 + ty * 4]);
            ulonglong2 b0 = *reinterpret_cast<const ulonglong2*>(&sB[kk * 128 + tx * 8]);
            ulonglong2 b1 = *reinterpret_cast<const ulonglong2*>(&sB[kk * 128 + tx * 8 + 4]);
            unsigned long long a0 = dupr(a4.x), a1 = dupr(a4.y);
            unsigned long long a2 = dupr(a4.z), a3 = dupr(a4.w);
            fma2(acc[0][0].u, a0, b0.x); fma2(acc[0][1].u, a0, b0.y);
            fma2(acc[0][2].u, a0, b1.x); fma2(acc[0][3].u, a0, b1.y);
            fma2(acc[1][0].u, a1, b0.x); fma2(acc[1][1].u, a1, b0.y);
            fma2(acc[1][2].u, a1, b1.x); fma2(acc[1][3].u, a1, b1.y);
            fma2(acc[2][0].u, a2, b0.x); fma2(acc[2][1].u, a2, b0.y);
            fma2(acc[2][2].u, a2, b1.x); fma2(acc[2][3].u, a2, b1.y);
            fma2(acc[3][0].u, a3, b0.x); fma2(acc[3][1].u, a3, b0.y);
            fma2(acc[3][2].u, a3, b1.x); fma2(acc[3][3].u, a3, b1.y);
        }
        __syncthreads();
    }
    const int j0 = (c0 >> 2) + tx * 2, j1 = j0 + 1;
    const float bi0 = b_e[j0], bf0 = b_e[NH + j0], bg0 = b_e[2 * NH + j0], bo0 = b_e[3 * NH + j0];
    const float bi1 = b_e[j1], bf1 = b_e[NH + j1], bg1 = b_e[2 * NH + j1], bo1 = b_e[3 * NH + j1];
#pragma unroll
    for (int i = 0; i < 4; i++) {
        size_t r = r0 + ty * 4 + i;
        float4 v0 = make_float4(acc[i][0].f[0] + bi0, acc[i][0].f[1] + bf0,
                                acc[i][1].f[0] + bg0, acc[i][1].f[1] + bo0);
        float4 v1 = make_float4(acc[i][2].f[0] + bi1, acc[i][2].f[1] + bf1,
                                acc[i][3].f[0] + bg1, acc[i][3].f[1] + bo1);
        *reinterpret_cast<float4*>(&g_gx[r * NG + c0 + tx * 8])     = v0;
        *reinterpret_cast<float4*>(&g_gx[r * NG + c0 + tx * 8 + 4]) = v1;
    }
}

// ---------------- persistent scan (encoder / decoder) -----------------------
// Batch is tiled into 16 groups of 32 rows. Each block hosts TWO independent
// jobs in disjoint warp halves: warps 0-7 = (group g, col-tile by), warps
// 8-15 = (group g+8, same by). Jobs share the resident weight tile but have
// private A buffers, private split-k reduction buffers, private NAMED
// barriers (bar.sync 1/2, 256) and private per-group flag barriers — no
// block-wide sync in the loop, so one job's barrier/memory stalls hide
// behind the other's compute. Per job: stage 32x256 h tile, split-k GEMM
// (warps: k-half 0 / k-half 1), SMEM reduce, gates, registers hold c/h.
// Decoder fuses recon[t-1] = h@Wop + bop and runs a 513th pseudo-step.
template <bool ENC>
__global__ void __launch_bounds__(512, 1) k_scan(unsigned ebase,
                                                 const float* __restrict__ Wop,
                                                 const float* __restrict__ bop,
                                                 float* __restrict__ out) {
    extern __shared__ float sm[];
    float* sW  = sm;                       // [256 k][64 gate-cols]   64 KB resident
    float* sA  = sm + NH * 64;             // 2 x [256 k][32 rows]    64 KB
    float* sR  = sA + 2 * NH * 32;         // 2 x [16][128] partials  16 KB
    float* sRp = sR + 2 * 16 * 128;        // 2 x [128] pred partials  1 KB
    float* sP  = sRp + 2 * 128;            // [256 k][4] Wop tile      4 KB

    const int tid  = threadIdx.x;
    const int jid  = tid >> 8;             // job 0 / 1
    const int jtid = tid & 255;
    const int barid = 1 + jid;
    const int by = blockIdx.x >> 3;
    const int g  = (blockIdx.x & 7) + jid * 8;
    const int b0 = g * 32;
    const int c0 = by * 64;
    const int sub = jtid & 127;
    const int kb  = (jtid >> 7) * 128;     // k-half base
    const int tx = sub & 15, ty = sub >> 4;   // ty in [0,8): 8 row-quads
    const int j  = (c0 >> 2) + tx;
    const int pr = sub >> 2, pc = sub & 3;    // 32 rows x 4 obs-cols
    const int sr  = jtid & 31;                // staging row
    const int sk0 = (jtid >> 5) * 32;         // staging k-chunk
    float* sAj  = sA + jid * NH * 32;
    float* sRj  = sR + jid * 16 * 128;
    float* sRpj = sRp + jid * 128;
    const bool lower = (jtid < 128);

    // preload shared weight tile + Wop tile (all 512 threads, once)
    const float* __restrict__ Wg = ENC ? g_Wr_he : g_Wr_d;
    for (int q = tid; q < NH * 16; q += 512) {
        int k = q >> 4, cc = (q & 15) * 4;
        *reinterpret_cast<float4*>(&sW[k * 64 + cc]) =
            *reinterpret_cast<const float4*>(&Wg[(size_t)k * NG + c0 + cc]);
    }
    float bopv = 0.0f;
    float4 bv = make_float4(0.f, 0.f, 0.f, 0.f);
    if (!ENC) {
        for (int q = tid; q < NH * 4; q += 512)
            sP[q] = Wop[(q >> 2) * NOBS + by * 4 + (q & 3)];
        bv = *reinterpret_cast<const float4*>(&g_br_d[c0 + tx * 4]);
        bopv = bop[by * 4 + pc];
    }

    float rc[4], rh[4];
    int rlen[4];
#pragma unroll
    for (int i = 0; i < 4; i++) {
        const int b = b0 + ty * 4 + i;
        if (ENC) {
            rc[i] = 0.0f; rh[i] = 0.0f; rlen[i] = g_len[b];
            if (lower) g_h[0][b * NH + j] = 0.0f;     // zero initial hidden
        } else {
            float v = g_h[0][b * NH + j];             // ctx from k_latctx
            rc[i] = v; rh[i] = v; rlen[i] = 0;
        }
    }
    __syncthreads();                                   // sW/sP (+zeroing local) ready
    if (ENC) job_flag_barrier(barid, g, by, ebase + 1);   // zero-init visible in group

    // gx prefetch for step 0 (lower half only)
    float4 gv[4];
    if (ENC && lower) {
#pragma unroll
        for (int i = 0; i < 4; i++)
            gv[i] = *reinterpret_cast<const float4*>(
                &g_gx[(size_t)(b0 + ty * 4 + i) * NG + c0 + tx * 4]);
    }

    const int TEND = ENC ? NT : NT + 1;
    for (int t = 0; t < TEND; t++) {
        const float* __restrict__ h_in = g_h[t & 1];
        float* __restrict__ h_out = g_h[(t & 1) ^ 1];

        // ---- stage this job's 32x256 h tile -> sAj[k][row] ----
        {
            float4 tmp[8];
#pragma unroll
            for (int i = 0; i < 8; i++)
                tmp[i] = *reinterpret_cast<const float4*>(
                    &h_in[(size_t)(b0 + sr) * NH + sk0 + 4 * i]);
#pragma unroll
            for (int i = 0; i < 8; i++) {
                sAj[(sk0 + 4 * i + 0) * 32 + sr] = tmp[i].x;
                sAj[(sk0 + 4 * i + 1) * 32 + sr] = tmp[i].y;
                sAj[(sk0 + 4 * i + 2) * 32 + sr] = tmp[i].z;
                sAj[(sk0 + 4 * i + 3) * 32 + sr] = tmp[i].w;
            }
        }
        barj(barid);

        F2U acc[4][2];
#pragma unroll
        for (int i = 0; i < 4; i++) { acc[i][0].u = 0ull; acc[i][1].u = 0ull; }
        float accp = 0.0f;

        // ---- split-k GEMM: this k-half covers [kb, kb+128) ----
        float4 a_cur = *reinterpret_cast<const float4*>(&sAj[kb * 32 + ty * 4]);
        ulonglong2 b_cur = *reinterpret_cast<const ulonglong2*>(&sW[kb * 64 + tx * 4]);
        float p_cur = 0.0f, w_cur = 0.0f;
        if (!ENC) { p_cur = sAj[kb * 32 + pr]; w_cur = sP[kb * 4 + pc]; }
#pragma unroll 8
        for (int k = kb; k < kb + 127; k++) {
            float4 a_nxt = *reinterpret_cast<const float4*>(&sAj[(k + 1) * 32 + ty * 4]);
            ulonglong2 b_nxt = *reinterpret_cast<const ulonglong2*>(&sW[(k + 1) * 64 + tx * 4]);
            float p_nxt = 0.0f, w_nxt = 0.0f;
            if (!ENC) { p_nxt = sAj[(k + 1) * 32 + pr]; w_nxt = sP[(k + 1) * 4 + pc]; }
            unsigned long long a0 = dupr(a_cur.x), a1 = dupr(a_cur.y);
            unsigned long long a2 = dupr(a_cur.z), a3 = dupr(a_cur.w);
            fma2(acc[0][0].u, a0, b_cur.x); fma2(acc[0][1].u, a0, b_cur.y);
            fma2(acc[1][0].u, a1, b_cur.x); fma2(acc[1][1].u, a1, b_cur.y);
            fma2(acc[2][0].u, a2, b_cur.x); fma2(acc[2][1].u, a2, b_cur.y);
            fma2(acc[3][0].u, a3, b_cur.x); fma2(acc[3][1].u, a3, b_cur.y);
            if (!ENC) accp = fmaf(p_cur, w_cur, accp);
            a_cur = a_nxt; b_cur = b_nxt; p_cur = p_nxt; w_cur = w_nxt;
        }
        {   // final k of this half
            unsigned long long a0 = dupr(a_cur.x), a1 = dupr(a_cur.y);
            unsigned long long a2 = dupr(a_cur.z), a3 = dupr(a_cur.w);
            fma2(acc[0][0].u, a0, b_cur.x); fma2(acc[0][1].u, a0, b_cur.y);
            fma2(acc[1][0].u, a1, b_cur.x); fma2(acc[1][1].u, a1, b_cur.y);
            fma2(acc[2][0].u, a2, b_cur.x); fma2(acc[2][1].u, a2, b_cur.y);
            fma2(acc[3][0].u, a3, b_cur.x); fma2(acc[3][1].u, a3, b_cur.y);
            if (!ENC) accp = fmaf(p_cur, w_cur, accp);
        }

        // ---- cross-half reduction: upper k-half publishes partials ----
        if (!lower) {
#pragma unroll
            for (int i = 0; i < 4; i++) {
                sRj[(i * 4 + 0) * 128 + sub] = acc[i][0].f[0];
                sRj[(i * 4 + 1) * 128 + sub] = acc[i][0].f[1];
                sRj[(i * 4 + 2) * 128 + sub] = acc[i][1].f[0];
                sRj[(i * 4 + 3) * 128 + sub] = acc[i][1].f[1];
            }
            if (!ENC) sRpj[sub] = accp;
        }
        barj(barid);

        if (lower && (ENC || t < NT)) {
#pragma unroll
            for (int i = 0; i < 4; i++) {
                const int b = b0 + ty * 4 + i;
                float zi = acc[i][0].f[0] + sRj[(i * 4 + 0) * 128 + sub];
                float zf = acc[i][0].f[1] + sRj[(i * 4 + 1) * 128 + sub];
                float zg = acc[i][1].f[0] + sRj[(i * 4 + 2) * 128 + sub];
                float zo = acc[i][1].f[1] + sRj[(i * 4 + 3) * 128 + sub];
                if (ENC) { zi += gv[i].x; zf += gv[i].y; zg += gv[i].z; zo += gv[i].w; }
                else     { zi += bv.x;    zf += bv.y;    zg += bv.z;    zo += bv.w; }
                float ig = fsig(zi), fg = fsig(zf), gg = ftanh(zg), og = fsig(zo);
                float nc = fg * rc[i] + ig * gg;
                float nh = og * ftanh(nc);
                if (ENC) {
                    bool m = (t < rlen[i]);                 // prefix mask
                    rc[i] = m ? nc : rc[i];
                    rh[i] = m ? nh : rh[i];
                } else {
                    rc[i] = nc; rh[i] = nh;
                }
                h_out[b * NH + j] = rh[i];
            }
        }
        if (!ENC && lower && t >= 1)
            out[((size_t)(b0 + pr) * NT + (t - 1)) * NOBS + by * 4 + pc] =
                accp + sRpj[sub] + bopv;

        // prefetch gx for step t+1 (latency hidden behind the flag wait)
        if (ENC && lower && t + 1 < NT) {
#pragma unroll
            for (int i = 0; i < 4; i++)
                gv[i] = *reinterpret_cast<const float4*>(
                    &g_gx[(size_t)(t + 1) * NB * NG + (size_t)(b0 + ty * 4 + i) * NG + c0 + tx * 4]);
        }

        if (t + 1 < TEND)
            job_flag_barrier(barid, g, by,
                             ebase + (ENC ? (unsigned)(t + 2) : (unsigned)(t + 1)));
    }
}

// ---------------- latent + context (fused) -----------------------------------
__global__ void k_latctx(const float* __restrict__ Wlp, const float* __restrict__ blp,
                         const float* __restrict__ Wle, const float* __restrict__ ble,
                         float* __restrict__ out) {
    __shared__ float slat[NLAT];
    const int b = blockIdx.x, tid = threadIdx.x;
    const int l = tid >> 4, sub = tid & 15;
    const float* h = g_h[0];                 // final encoder h (512 steps -> buf 0)
    float s = 0.0f;
    for (int k = sub; k < NH; k += 16) s += h[b * NH + k] * Wlp[k * NLAT + l];
#pragma unroll
    for (int off = 8; off; off >>= 1) s += __shfl_xor_sync(0xffffffffu, s, off);
    if (sub == 0) {
        float v = s + blp[l];
        slat[l] = v;
        out[(size_t)NB * NT * NOBS + (size_t)b * NLAT + l] = v;
    }
    __syncthreads();
    float s2 = ble[tid];
#pragma unroll
    for (int l2 = 0; l2 < NLAT; l2++) s2 += slat[l2] * Wle[l2 * NH + tid];
    g_h[0][b * NH + tid] = s2 > 0.0f ? s2 : 0.01f * s2;   // ctx -> initial (c,h)
}

// ---------------- driver -----------------------------------------------------
extern "C" void kernel_launch(void* const* d_in, const int* in_sizes, int n_in,
                              void* d_out, int out_size) {
    (void)in_sizes; (void)n_in; (void)out_size;
    const float* x    = (const float*)d_in[0];
    const void*  mask = d_in[1];
    const float* Wip  = (const float*)d_in[2];
    const float* bip  = (const float*)d_in[3];
    const float* Wi_e = (const float*)d_in[4];
    const float* Wh_e = (const float*)d_in[5];
    const float* b_e  = (const float*)d_in[6];
    const float* Wlp  = (const float*)d_in[7];
    const float* blp  = (const float*)d_in[8];
    const float* Wle  = (const float*)d_in[9];
    const float* ble  = (const float*)d_in[10];
    const float* Wi_d = (const float*)d_in[11];
    const float* Wh_d = (const float*)d_in[12];
    const float* b_d  = (const float*)d_in[13];
    const float* Wop  = (const float*)d_in[14];
    const float* bop  = (const float*)d_in[15];
    float* out = (float*)d_out;

    // smem: sW 64K + sA 2x32K + sR 2x8K + sRp 2x0.5K + sP 4K = 149 KB
    const size_t smem = (size_t)(NH * 64 + 2 * NH * 32 + 2 * 16 * 128 + 2 * 128 + NH * 4)
                        * sizeof(float);
    cudaFuncSetAttribute(k_scan<true>,  cudaFuncAttributeMaxDynamicSharedMemorySize, (int)smem);
    cudaFuncSetAttribute(k_scan<false>, cudaFuncAttributeMaxDynamicSharedMemorySize, (int)smem);

    // 6 graph nodes total
    k_setup<<<1024, 256>>>(mask, Wi_e, Wh_e, Wi_d, Wh_d, b_d);
    k_inproj<<<dim3(NB * NT / 64, NH / 64), 256>>>(x, Wip, bip);
    k_gatesx<<<dim3(NG / 128, NB * NT / 64), 256>>>(b_e);
    k_scan<true><<<NBLK, 512, smem>>>(0u, nullptr, nullptr, nullptr);
    k_latctx<<<NB, 256>>>(Wlp, blp, Wle, ble, out);
    k_scan<false><<<NBLK, 512, smem>>>(512u, Wop, bop, out);
}

// round 14
// speedup vs baseline: 1.2732x; 1.0371x over previous
#include <cuda_runtime.h>

// Problem dimensions
static constexpr int NB = 512;   // batch
static constexpr int NT = 512;   // time
static constexpr int NOBS = 64;  // obs dim
static constexpr int NH = 256;   // hidden
static constexpr int NG = 1024;  // 4*H
static constexpr int NLAT = 16;  // latent
static constexpr int NBLK = 128; // persistent grid

// ---------------- scratch (device globals; no allocation allowed) ----------
__device__ float g_xp[(size_t)NT * NB * NH];   // [t*NB+b][h] = leaky(x@Wip+bip)
__device__ float g_Wr_ie[NH * NG];             // Wi_e reordered: [k][4j+g]
__device__ float g_Wr_he[NH * NG];             // Wh_e reordered
__device__ float g_Wr_d[NH * NG];              // (Wi_d + Wh_d) reordered
__device__ float g_br_e[NG];                   // b_e reordered
__device__ float g_br_d[NG];                   // b_d reordered
__device__ float g_h[2][NB * NH];              // ping-pong hidden state
__device__ int   g_len[NB];                    // per-row valid length (prefix mask)
__device__ unsigned g_flag[16][16 * 32];       // per-(group,block) step flags, 128B stride

// ---------------- helpers ---------------------------------------------------
union F2U { unsigned long long u; float f[2]; };

__device__ __forceinline__ void fma2(unsigned long long& d, unsigned long long a,
                                     unsigned long long b) {
    asm("fma.rn.f32x2 %0, %1, %2, %0;" : "+l"(d) : "l"(a), "l"(b));
}

__device__ __forceinline__ unsigned long long dupr(float x) {
    unsigned long long r;
    asm("mov.b64 %0, {%1, %1};" : "=l"(r) : "f"(x));
    return r;
}

__device__ __forceinline__ float fsig(float x) {
    return __fdividef(1.0f, 1.0f + __expf(-x));
}
__device__ __forceinline__ float ftanh(float x) {
    return 1.0f - __fdividef(2.0f, __expf(2.0f * x) + 1.0f);
}

// named barrier over the 256 threads of one job (barid 1 or 2)
__device__ __forceinline__ void barj(int barid) {
    asm volatile("bar.sync %0, 256;" :: "r"(barid) : "memory");
}

__device__ __forceinline__ void flag_signal(int g, int myslot, unsigned target) {
    asm volatile("st.release.gpu.global.b32 [%0], %1;"
                 :: "l"(&g_flag[g][myslot * 32]), "r"(target) : "memory");
}

// every warp polls the 16 slots in parallel (lanes 0-15)
__device__ __forceinline__ void flag_wait(int g, unsigned target) {
    const int lane = threadIdx.x & 31;
    if (lane < 16) {
        unsigned cur;
        do {
            asm volatile("ld.acquire.gpu.global.b32 %0, [%1];"
                         : "=r"(cur) : "l"(&g_flag[g][lane * 32]) : "memory");
        } while ((int)(cur - target) < 0);
    }
    __syncwarp();
}

// ---------------- setup: weight reorder + mask lengths + flag reset ----------
__global__ void k_setup(const void* __restrict__ mask,
                        const float* __restrict__ Wi_e, const float* __restrict__ Wh_e,
                        const float* __restrict__ Wi_d, const float* __restrict__ Wh_d,
                        const float* __restrict__ b_e, const float* __restrict__ b_d) {
    const int idx = blockIdx.x * 256 + threadIdx.x;   // grid 1024 x 256 = NH*NG
    {
        int k = idx >> 10, c = idx & 1023;
        int g = c & 3, j = c >> 2;
        int src = k * NG + g * NH + j;
        g_Wr_ie[idx] = Wi_e[src];
        g_Wr_he[idx] = Wh_e[src];
        g_Wr_d[idx]  = Wi_d[src] + Wh_d[src];   // decoder input == hidden -> fold
    }
    if (idx < NG) {
        int g = idx & 3, j = idx >> 2;
        g_br_e[idx] = b_e[g * NH + j];
        g_br_d[idx] = b_d[g * NH + j];
    }
    if (idx < 16 * 16 * 32) ((unsigned*)g_flag)[idx] = 0u;
    if (blockIdx.x < NB) {
        const int b = blockIdx.x, tid = threadIdx.x;
        const bool u8 = (((const int*)mask)[0] != 1);
        int cnt = 0;
        for (int t = tid; t < NT; t += 256)
            cnt += u8 ? (((const unsigned char*)mask)[(size_t)b * NT + t] != 0)
                      : (((const int*)mask)[(size_t)b * NT + t] != 0);
#pragma unroll
        for (int off = 16; off; off >>= 1) cnt += __shfl_xor_sync(0xffffffffu, cnt, off);
        __shared__ int sred[8];
        if ((tid & 31) == 0) sred[tid >> 5] = cnt;
        __syncthreads();
        if (tid == 0) {
            int s = 0;
#pragma unroll
            for (int i = 0; i < 8; i++) s += sred[i];
            g_len[b] = s;
        }
    }
}

// ---------------- K1: input projection  xp = leaky(x @ Wip + bip) -----------
__global__ void __launch_bounds__(256) k_inproj(const float* __restrict__ x,
                                                const float* __restrict__ Wip,
                                                const float* __restrict__ bip) {
    __shared__ __align__(16) float sA[16][64];
    __shared__ __align__(16) float sB[16][64];
    const int tid = threadIdx.x;
    const int r0 = blockIdx.x * 64, c0 = blockIdx.y * 64;
    const int tx = tid & 15, ty = tid >> 4;
    const int am = tid >> 2, ak = (tid & 3) * 4;
    const int bk = tid >> 4, bc = (tid & 15) * 4;
    float acc[4][4] = {};
    for (int k0 = 0; k0 < NOBS; k0 += 16) {
        int r = r0 + am;
        int t = r >> 9;
        int b = r & (NB - 1);
        float4 av = *reinterpret_cast<const float4*>(&x[((size_t)b * NT + t) * NOBS + k0 + ak]);
        sA[ak + 0][am] = av.x; sA[ak + 1][am] = av.y;
        sA[ak + 2][am] = av.z; sA[ak + 3][am] = av.w;
        float4 bv = *reinterpret_cast<const float4*>(&Wip[(size_t)(k0 + bk) * NH + c0 + bc]);
        *reinterpret_cast<float4*>(&sB[bk][bc]) = bv;
        __syncthreads();
#pragma unroll
        for (int kk = 0; kk < 16; kk++) {
            float4 a4 = *reinterpret_cast<const float4*>(&sA[kk][ty * 4]);
            float4 b4 = *reinterpret_cast<const float4*>(&sB[kk][tx * 4]);
            float ar[4] = {a4.x, a4.y, a4.z, a4.w};
            float br[4] = {b4.x, b4.y, b4.z, b4.w};
#pragma unroll
            for (int i = 0; i < 4; i++)
#pragma unroll
                for (int jj = 0; jj < 4; jj++)
                    acc[i][jj] += ar[i] * br[jj];
        }
        __syncthreads();
    }
#pragma unroll
    for (int i = 0; i < 4; i++) {
        int r = r0 + ty * 4 + i;
        float4 v;
        float z0 = acc[i][0] + bip[c0 + tx * 4 + 0];
        float z1 = acc[i][1] + bip[c0 + tx * 4 + 1];
        float z2 = acc[i][2] + bip[c0 + tx * 4 + 2];
        float z3 = acc[i][3] + bip[c0 + tx * 4 + 3];
        v.x = z0 > 0.0f ? z0 : 0.01f * z0;
        v.y = z1 > 0.0f ? z1 : 0.01f * z1;
        v.z = z2 > 0.0f ? z2 : 0.01f * z2;
        v.w = z3 > 0.0f ? z3 : 0.01f * z3;
        *reinterpret_cast<float4*>(&g_xp[(size_t)r * NH + c0 + tx * 4]) = v;
    }
}

// ---------------- encoder scan with FUSED input-gate GEMM --------------------
// Batch tiled into 16 groups of 32 rows; block hosts jobs (g, g+8) in warp
// halves (named barriers 1/2). Per step t: stage h[t] (32x256) -> sAj, split-k
// h-GEMM ACCUMULATING onto the zx partials computed LAST step, reduce both
// halves once, gates, h_out, signal; then stage xp[t+1] and run the x-GEMM
// (zx for t+1, bias folded into k-half-0 init) in the barrier-wait window.
// No gx buffer, no gx DRAM traffic, gatesx kernel deleted.
__global__ void __launch_bounds__(512, 1) k_escan() {
    extern __shared__ float sm[];
    float* sWh = sm;                       // [256 k][64]  Wh_e tile   64 KB
    float* sWi = sWh + NH * 64;            // [256 k][64]  Wi_e tile   64 KB
    float* sA  = sWi + NH * 64;            // 2 x [256 k][32 rows]     64 KB
    float* sR  = sA + 2 * NH * 32;         // 2 x [16][128] partials   16 KB

    const int tid  = threadIdx.x;
    const int jid  = tid >> 8;
    const int jtid = tid & 255;
    const int barid = 1 + jid;
    const int by = blockIdx.x >> 3;
    const int g  = (blockIdx.x & 7) + jid * 8;
    const int b0 = g * 32;
    const int c0 = by * 64;
    const int sub = jtid & 127;
    const int kb  = (jtid >> 7) * 128;
    const int tx = sub & 15, ty = sub >> 4;
    const int j  = (c0 >> 2) + tx;
    const int sr  = jtid & 31;
    const int sk0 = (jtid >> 5) * 32;
    float* sAj = sA + jid * NH * 32;
    float* sRj = sR + jid * 16 * 128;
    const bool lower = (jtid < 128);

    for (int q = tid; q < NH * 16; q += 512) {
        int k = q >> 4, cc = (q & 15) * 4;
        *reinterpret_cast<float4*>(&sWh[k * 64 + cc]) =
            *reinterpret_cast<const float4*>(&g_Wr_he[(size_t)k * NG + c0 + cc]);
        *reinterpret_cast<float4*>(&sWi[k * 64 + cc]) =
            *reinterpret_cast<const float4*>(&g_Wr_ie[(size_t)k * NG + c0 + cc]);
    }
    const float4 bv = *reinterpret_cast<const float4*>(&g_br_e[c0 + tx * 4]);

    float rc[4], rh[4];
    int rlen[4];
#pragma unroll
    for (int i = 0; i < 4; i++) {
        const int b = b0 + ty * 4 + i;
        rc[i] = 0.0f; rh[i] = 0.0f; rlen[i] = g_len[b];
        if (lower) g_h[0][b * NH + j] = 0.0f;
    }
    __syncthreads();                       // weights + zero-init done (block-wide)
    if (jtid == 0) flag_signal(g, by, 1u); // h[0] ready (this block's share)

    F2U acc[4][2];

    // helper lambda-free macro-style GEMM: accumulate A(sAj) @ W over [kb,kb+128)
    // (written inline twice below to keep register allocation tight)

    // ---- prologue: zx for step 0 ----
    {
        float4 tmp[8];
#pragma unroll
        for (int i = 0; i < 8; i++)
            tmp[i] = *reinterpret_cast<const float4*>(
                &g_xp[(size_t)(b0 + sr) * NH + sk0 + 4 * i]);
#pragma unroll
        for (int i = 0; i < 8; i++) {
            sAj[(sk0 + 4 * i + 0) * 32 + sr] = tmp[i].x;
            sAj[(sk0 + 4 * i + 1) * 32 + sr] = tmp[i].y;
            sAj[(sk0 + 4 * i + 2) * 32 + sr] = tmp[i].z;
            sAj[(sk0 + 4 * i + 3) * 32 + sr] = tmp[i].w;
        }
    }
    barj(barid);
#pragma unroll
    for (int i = 0; i < 4; i++) {
        if (kb == 0) {
            acc[i][0].f[0] = bv.x; acc[i][0].f[1] = bv.y;
            acc[i][1].f[0] = bv.z; acc[i][1].f[1] = bv.w;
        } else { acc[i][0].u = 0ull; acc[i][1].u = 0ull; }
    }
    {
        float4 a_cur = *reinterpret_cast<const float4*>(&sAj[kb * 32 + ty * 4]);
        ulonglong2 b_cur = *reinterpret_cast<const ulonglong2*>(&sWi[kb * 64 + tx * 4]);
#pragma unroll 8
        for (int k = kb; k < kb + 127; k++) {
            float4 a_nxt = *reinterpret_cast<const float4*>(&sAj[(k + 1) * 32 + ty * 4]);
            ulonglong2 b_nxt = *reinterpret_cast<const ulonglong2*>(&sWi[(k + 1) * 64 + tx * 4]);
            unsigned long long a0 = dupr(a_cur.x), a1 = dupr(a_cur.y);
            unsigned long long a2 = dupr(a_cur.z), a3 = dupr(a_cur.w);
            fma2(acc[0][0].u, a0, b_cur.x); fma2(acc[0][1].u, a0, b_cur.y);
            fma2(acc[1][0].u, a1, b_cur.x); fma2(acc[1][1].u, a1, b_cur.y);
            fma2(acc[2][0].u, a2, b_cur.x); fma2(acc[2][1].u, a2, b_cur.y);
            fma2(acc[3][0].u, a3, b_cur.x); fma2(acc[3][1].u, a3, b_cur.y);
            a_cur = a_nxt; b_cur = b_nxt;
        }
        unsigned long long a0 = dupr(a_cur.x), a1 = dupr(a_cur.y);
        unsigned long long a2 = dupr(a_cur.z), a3 = dupr(a_cur.w);
        fma2(acc[0][0].u, a0, b_cur.x); fma2(acc[0][1].u, a0, b_cur.y);
        fma2(acc[1][0].u, a1, b_cur.x); fma2(acc[1][1].u, a1, b_cur.y);
        fma2(acc[2][0].u, a2, b_cur.x); fma2(acc[2][1].u, a2, b_cur.y);
        fma2(acc[3][0].u, a3, b_cur.x); fma2(acc[3][1].u, a3, b_cur.y);
    }
    barj(barid);            // x-GEMM reads of sAj done
    flag_wait(g, 1u);       // all peers' h[0] zeros visible

    for (int t = 0; t < NT; t++) {
        const float* __restrict__ h_in = g_h[t & 1];
        float* __restrict__ h_out = g_h[(t & 1) ^ 1];

        // ---- stage h[t] tile ----
        {
            float4 tmp[8];
#pragma unroll
            for (int i = 0; i < 8; i++)
                tmp[i] = *reinterpret_cast<const float4*>(
                    &h_in[(size_t)(b0 + sr) * NH + sk0 + 4 * i]);
#pragma unroll
            for (int i = 0; i < 8; i++) {
                sAj[(sk0 + 4 * i + 0) * 32 + sr] = tmp[i].x;
                sAj[(sk0 + 4 * i + 1) * 32 + sr] = tmp[i].y;
                sAj[(sk0 + 4 * i + 2) * 32 + sr] = tmp[i].z;
                sAj[(sk0 + 4 * i + 3) * 32 + sr] = tmp[i].w;
            }
        }
        barj(barid);

        // ---- h-GEMM accumulating onto zx partials ----
        {
            float4 a_cur = *reinterpret_cast<const float4*>(&sAj[kb * 32 + ty * 4]);
            ulonglong2 b_cur = *reinterpret_cast<const ulonglong2*>(&sWh[kb * 64 + tx * 4]);
#pragma unroll 8
            for (int k = kb; k < kb + 127; k++) {
                float4 a_nxt = *reinterpret_cast<const float4*>(&sAj[(k + 1) * 32 + ty * 4]);
                ulonglong2 b_nxt = *reinterpret_cast<const ulonglong2*>(&sWh[(k + 1) * 64 + tx * 4]);
                unsigned long long a0 = dupr(a_cur.x), a1 = dupr(a_cur.y);
                unsigned long long a2 = dupr(a_cur.z), a3 = dupr(a_cur.w);
                fma2(acc[0][0].u, a0, b_cur.x); fma2(acc[0][1].u, a0, b_cur.y);
                fma2(acc[1][0].u, a1, b_cur.x); fma2(acc[1][1].u, a1, b_cur.y);
                fma2(acc[2][0].u, a2, b_cur.x); fma2(acc[2][1].u, a2, b_cur.y);
                fma2(acc[3][0].u, a3, b_cur.x); fma2(acc[3][1].u, a3, b_cur.y);
                a_cur = a_nxt; b_cur = b_nxt;
            }
            unsigned long long a0 = dupr(a_cur.x), a1 = dupr(a_cur.y);
            unsigned long long a2 = dupr(a_cur.z), a3 = dupr(a_cur.w);
            fma2(acc[0][0].u, a0, b_cur.x); fma2(acc[0][1].u, a0, b_cur.y);
            fma2(acc[1][0].u, a1, b_cur.x); fma2(acc[1][1].u, a1, b_cur.y);
            fma2(acc[2][0].u, a2, b_cur.x); fma2(acc[2][1].u, a2, b_cur.y);
            fma2(acc[3][0].u, a3, b_cur.x); fma2(acc[3][1].u, a3, b_cur.y);
        }

        // ---- cross-half reduction ----
        if (!lower) {
#pragma unroll
            for (int i = 0; i < 4; i++) {
                sRj[(i * 4 + 0) * 128 + sub] = acc[i][0].f[0];
                sRj[(i * 4 + 1) * 128 + sub] = acc[i][0].f[1];
                sRj[(i * 4 + 2) * 128 + sub] = acc[i][1].f[0];
                sRj[(i * 4 + 3) * 128 + sub] = acc[i][1].f[1];
            }
        }
        barj(barid);

        if (lower) {
#pragma unroll
            for (int i = 0; i < 4; i++) {
                const int b = b0 + ty * 4 + i;
                float zi = acc[i][0].f[0] + sRj[(i * 4 + 0) * 128 + sub];
                float zf = acc[i][0].f[1] + sRj[(i * 4 + 1) * 128 + sub];
                float zg = acc[i][1].f[0] + sRj[(i * 4 + 2) * 128 + sub];
                float zo = acc[i][1].f[1] + sRj[(i * 4 + 3) * 128 + sub];
                float ig = fsig(zi), fg = fsig(zf), gg = ftanh(zg), og = fsig(zo);
                float nc = fg * rc[i] + ig * gg;
                float nh = og * ftanh(nc);
                bool m = (t < rlen[i]);
                rc[i] = m ? nc : rc[i];
                rh[i] = m ? nh : rh[i];
                h_out[b * NH + j] = rh[i];
            }
        }
        barj(barid);                                   // h_out written by whole job
        if (t + 1 < NT) {
            if (jtid == 0) flag_signal(g, by, (unsigned)(t + 2));

            // ---- stage xp[t+1] and run x-GEMM in the wait window ----
            {
                float4 tmp[8];
#pragma unroll
                for (int i = 0; i < 8; i++)
                    tmp[i] = *reinterpret_cast<const float4*>(
                        &g_xp[((size_t)(t + 1) * NB + b0 + sr) * NH + sk0 + 4 * i]);
#pragma unroll
                for (int i = 0; i < 8; i++) {
                    sAj[(sk0 + 4 * i + 0) * 32 + sr] = tmp[i].x;
                    sAj[(sk0 + 4 * i + 1) * 32 + sr] = tmp[i].y;
                    sAj[(sk0 + 4 * i + 2) * 32 + sr] = tmp[i].z;
                    sAj[(sk0 + 4 * i + 3) * 32 + sr] = tmp[i].w;
                }
            }
            barj(barid);
#pragma unroll
            for (int i = 0; i < 4; i++) {
                if (kb == 0) {
                    acc[i][0].f[0] = bv.x; acc[i][0].f[1] = bv.y;
                    acc[i][1].f[0] = bv.z; acc[i][1].f[1] = bv.w;
                } else { acc[i][0].u = 0ull; acc[i][1].u = 0ull; }
            }
            {
                float4 a_cur = *reinterpret_cast<const float4*>(&sAj[kb * 32 + ty * 4]);
                ulonglong2 b_cur = *reinterpret_cast<const ulonglong2*>(&sWi[kb * 64 + tx * 4]);
#pragma unroll 8
                for (int k = kb; k < kb + 127; k++) {
                    float4 a_nxt = *reinterpret_cast<const float4*>(&sAj[(k + 1) * 32 + ty * 4]);
                    ulonglong2 b_nxt = *reinterpret_cast<const ulonglong2*>(&sWi[(k + 1) * 64 + tx * 4]);
                    unsigned long long a0 = dupr(a_cur.x), a1 = dupr(a_cur.y);
                    unsigned long long a2 = dupr(a_cur.z), a3 = dupr(a_cur.w);
                    fma2(acc[0][0].u, a0, b_cur.x); fma2(acc[0][1].u, a0, b_cur.y);
                    fma2(acc[1][0].u, a1, b_cur.x); fma2(acc[1][1].u, a1, b_cur.y);
                    fma2(acc[2][0].u, a2, b_cur.x); fma2(acc[2][1].u, a2, b_cur.y);
                    fma2(acc[3][0].u, a3, b_cur.x); fma2(acc[3][1].u, a3, b_cur.y);
                    a_cur = a_nxt; b_cur = b_nxt;
                }
                unsigned long long a0 = dupr(a_cur.x), a1 = dupr(a_cur.y);
                unsigned long long a2 = dupr(a_cur.z), a3 = dupr(a_cur.w);
                fma2(acc[0][0].u, a0, b_cur.x); fma2(acc[0][1].u, a0, b_cur.y);
                fma2(acc[1][0].u, a1, b_cur.x); fma2(acc[1][1].u, a1, b_cur.y);
                fma2(acc[2][0].u, a2, b_cur.x); fma2(acc[2][1].u, a2, b_cur.y);
                fma2(acc[3][0].u, a3, b_cur.x); fma2(acc[3][1].u, a3, b_cur.y);
            }
            barj(barid);                               // x-GEMM reads of sAj done
            flag_wait(g, (unsigned)(t + 2));           // peers' h[t+1] ready
        }
    }
}

// ---------------- decoder scan (R13, unchanged) ------------------------------
__global__ void __launch_bounds__(512, 1) k_dscan(unsigned ebase,
                                                  const float* __restrict__ Wop,
                                                  const float* __restrict__ bop,
                                                  float* __restrict__ out) {
    extern __shared__ float sm[];
    float* sW  = sm;                       // [256 k][64]             64 KB
    float* sA  = sm + NH * 64;             // 2 x [256 k][32 rows]    64 KB
    float* sR  = sA + 2 * NH * 32;         // 2 x [16][128] partials  16 KB
    float* sRp = sR + 2 * 16 * 128;        // 2 x [128] pred partials  1 KB
    float* sP  = sRp + 2 * 128;            // [256 k][4] Wop tile      4 KB

    const int tid  = threadIdx.x;
    const int jid  = tid >> 8;
    const int jtid = tid & 255;
    const int barid = 1 + jid;
    const int by = blockIdx.x >> 3;
    const int g  = (blockIdx.x & 7) + jid * 8;
    const int b0 = g * 32;
    const int c0 = by * 64;
    const int sub = jtid & 127;
    const int kb  = (jtid >> 7) * 128;
    const int tx = sub & 15, ty = sub >> 4;
    const int j  = (c0 >> 2) + tx;
    const int pr = sub >> 2, pc = sub & 3;
    const int sr  = jtid & 31;
    const int sk0 = (jtid >> 5) * 32;
    float* sAj  = sA + jid * NH * 32;
    float* sRj  = sR + jid * 16 * 128;
    float* sRpj = sRp + jid * 128;
    const bool lower = (jtid < 128);

    for (int q = tid; q < NH * 16; q += 512) {
        int k = q >> 4, cc = (q & 15) * 4;
        *reinterpret_cast<float4*>(&sW[k * 64 + cc]) =
            *reinterpret_cast<const float4*>(&g_Wr_d[(size_t)k * NG + c0 + cc]);
    }
    for (int q = tid; q < NH * 4; q += 512)
        sP[q] = Wop[(q >> 2) * NOBS + by * 4 + (q & 3)];
    const float4 bv = *reinterpret_cast<const float4*>(&g_br_d[c0 + tx * 4]);
    const float bopv = bop[by * 4 + pc];

    float rc[4], rh[4];
#pragma unroll
    for (int i = 0; i < 4; i++) {
        const int b = b0 + ty * 4 + i;
        float v = g_h[0][b * NH + j];
        rc[i] = v; rh[i] = v;
    }
    __syncthreads();

    const int TEND = NT + 1;
    for (int t = 0; t < TEND; t++) {
        const float* __restrict__ h_in = g_h[t & 1];
        float* __restrict__ h_out = g_h[(t & 1) ^ 1];

        {
            float4 tmp[8];
#pragma unroll
            for (int i = 0; i < 8; i++)
                tmp[i] = *reinterpret_cast<const float4*>(
                    &h_in[(size_t)(b0 + sr) * NH + sk0 + 4 * i]);
#pragma unroll
            for (int i = 0; i < 8; i++) {
                sAj[(sk0 + 4 * i + 0) * 32 + sr] = tmp[i].x;
                sAj[(sk0 + 4 * i + 1) * 32 + sr] = tmp[i].y;
                sAj[(sk0 + 4 * i + 2) * 32 + sr] = tmp[i].z;
                sAj[(sk0 + 4 * i + 3) * 32 + sr] = tmp[i].w;
            }
        }
        barj(barid);

        F2U acc[4][2];
#pragma unroll
        for (int i = 0; i < 4; i++) { acc[i][0].u = 0ull; acc[i][1].u = 0ull; }
        float accp = 0.0f;

        float4 a_cur = *reinterpret_cast<const float4*>(&sAj[kb * 32 + ty * 4]);
        ulonglong2 b_cur = *reinterpret_cast<const ulonglong2*>(&sW[kb * 64 + tx * 4]);
        float p_cur = sAj[kb * 32 + pr], w_cur = sP[kb * 4 + pc];
#pragma unroll 8
        for (int k = kb; k < kb + 127; k++) {
            float4 a_nxt = *reinterpret_cast<const float4*>(&sAj[(k + 1) * 32 + ty * 4]);
            ulonglong2 b_nxt = *reinterpret_cast<const ulonglong2*>(&sW[(k + 1) * 64 + tx * 4]);
            float p_nxt = sAj[(k + 1) * 32 + pr], w_nxt = sP[(k + 1) * 4 + pc];
            unsigned long long a0 = dupr(a_cur.x), a1 = dupr(a_cur.y);
            unsigned long long a2 = dupr(a_cur.z), a3 = dupr(a_cur.w);
            fma2(acc[0][0].u, a0, b_cur.x); fma2(acc[0][1].u, a0, b_cur.y);
            fma2(acc[1][0].u, a1, b_cur.x); fma2(acc[1][1].u, a1, b_cur.y);
            fma2(acc[2][0].u, a2, b_cur.x); fma2(acc[2][1].u, a2, b_cur.y);
            fma2(acc[3][0].u, a3, b_cur.x); fma2(acc[3][1].u, a3, b_cur.y);
            accp = fmaf(p_cur, w_cur, accp);
            a_cur = a_nxt; b_cur = b_nxt; p_cur = p_nxt; w_cur = w_nxt;
        }
        {
            unsigned long long a0 = dupr(a_cur.x), a1 = dupr(a_cur.y);
            unsigned long long a2 = dupr(a_cur.z), a3 = dupr(a_cur.w);
            fma2(acc[0][0].u, a0, b_cur.x); fma2(acc[0][1].u, a0, b_cur.y);
            fma2(acc[1][0].u, a1, b_cur.x); fma2(acc[1][1].u, a1, b_cur.y);
            fma2(acc[2][0].u, a2, b_cur.x); fma2(acc[2][1].u, a2, b_cur.y);
            fma2(acc[3][0].u, a3, b_cur.x); fma2(acc[3][1].u, a3, b_cur.y);
            accp = fmaf(p_cur, w_cur, accp);
        }

        if (!lower) {
#pragma unroll
            for (int i = 0; i < 4; i++) {
                sRj[(i * 4 + 0) * 128 + sub] = acc[i][0].f[0];
                sRj[(i * 4 + 1) * 128 + sub] = acc[i][0].f[1];
                sRj[(i * 4 + 2) * 128 + sub] = acc[i][1].f[0];
                sRj[(i * 4 + 3) * 128 + sub] = acc[i][1].f[1];
            }
            sRpj[sub] = accp;
        }
        barj(barid);

        if (lower && t < NT) {
#pragma unroll
            for (int i = 0; i < 4; i++) {
                const int b = b0 + ty * 4 + i;
                float zi = acc[i][0].f[0] + sRj[(i * 4 + 0) * 128 + sub] + bv.x;
                float zf = acc[i][0].f[1] + sRj[(i * 4 + 1) * 128 + sub] + bv.y;
                float zg = acc[i][1].f[0] + sRj[(i * 4 + 2) * 128 + sub] + bv.z;
                float zo = acc[i][1].f[1] + sRj[(i * 4 + 3) * 128 + sub] + bv.w;
                float ig = fsig(zi), fg = fsig(zf), gg = ftanh(zg), og = fsig(zo);
                float nc = fg * rc[i] + ig * gg;
                float nh = og * ftanh(nc);
                rc[i] = nc; rh[i] = nh;
                h_out[b * NH + j] = nh;
            }
        }
        if (lower && t >= 1)
            out[((size_t)(b0 + pr) * NT + (t - 1)) * NOBS + by * 4 + pc] =
                accp + sRpj[sub] + bopv;

        if (t + 1 < TEND) {
            barj(barid);
            if (jtid == 0) flag_signal(g, by, ebase + (unsigned)(t + 1));
            flag_wait(g, ebase + (unsigned)(t + 1));
        }
    }
}

// ---------------- latent + context (fused) -----------------------------------
__global__ void k_latctx(const float* __restrict__ Wlp, const float* __restrict__ blp,
                         const float* __restrict__ Wle, const float* __restrict__ ble,
                         float* __restrict__ out) {
    __shared__ float slat[NLAT];
    const int b = blockIdx.x, tid = threadIdx.x;
    const int l = tid >> 4, sub = tid & 15;
    const float* h = g_h[0];
    float s = 0.0f;
    for (int k = sub; k < NH; k += 16) s += h[b * NH + k] * Wlp[k * NLAT + l];
#pragma unroll
    for (int off = 8; off; off >>= 1) s += __shfl_xor_sync(0xffffffffu, s, off);
    if (sub == 0) {
        float v = s + blp[l];
        slat[l] = v;
        out[(size_t)NB * NT * NOBS + (size_t)b * NLAT + l] = v;
    }
    __syncthreads();
    float s2 = ble[tid];
#pragma unroll
    for (int l2 = 0; l2 < NLAT; l2++) s2 += slat[l2] * Wle[l2 * NH + tid];
    g_h[0][b * NH + tid] = s2 > 0.0f ? s2 : 0.01f * s2;
}

// ---------------- driver -----------------------------------------------------
extern "C" void kernel_launch(void* const* d_in, const int* in_sizes, int n_in,
                              void* d_out, int out_size) {
    (void)in_sizes; (void)n_in; (void)out_size;
    const float* x    = (const float*)d_in[0];
    const void*  mask = d_in[1];
    const float* Wip  = (const float*)d_in[2];
    const float* bip  = (const float*)d_in[3];
    const float* Wi_e = (const float*)d_in[4];
    const float* Wh_e = (const float*)d_in[5];
    const float* b_e  = (const float*)d_in[6];
    const float* Wlp  = (const float*)d_in[7];
    const float* blp  = (const float*)d_in[8];
    const float* Wle  = (const float*)d_in[9];
    const float* ble  = (const float*)d_in[10];
    const float* Wi_d = (const float*)d_in[11];
    const float* Wh_d = (const float*)d_in[12];
    const float* b_d  = (const float*)d_in[13];
    const float* Wop  = (const float*)d_in[14];
    const float* bop  = (const float*)d_in[15];
    float* out = (float*)d_out;

    // encoder smem: sWh 64K + sWi 64K + sA 64K + sR 16K = 208 KB
    const size_t smem_e = (size_t)(NH * 64 * 2 + 2 * NH * 32 + 2 * 16 * 128) * sizeof(float);
    // decoder smem: sW 64K + sA 64K + sR 16K + sRp 1K + sP 4K = 149 KB
    const size_t smem_d = (size_t)(NH * 64 + 2 * NH * 32 + 2 * 16 * 128 + 2 * 128 + NH * 4)
                          * sizeof(float);
    cudaFuncSetAttribute(k_escan, cudaFuncAttributeMaxDynamicSharedMemorySize, (int)smem_e);
    cudaFuncSetAttribute(k_dscan, cudaFuncAttributeMaxDynamicSharedMemorySize, (int)smem_d);

    // 5 graph nodes total
    k_setup<<<1024, 256>>>(mask, Wi_e, Wh_e, Wi_d, Wh_d, b_e, b_d);
    k_inproj<<<dim3(NB * NT / 64, NH / 64), 256>>>(x, Wip, bip);
    k_escan<<<NBLK, 512, smem_e>>>();
    k_latctx<<<NB, 256>>>(Wlp, blp, Wle, ble, out);
    k_dscan<<<NBLK, 512, smem_d>>>(513u, Wop, bop, out);
}

// round 15
// speedup vs baseline: 1.4191x; 1.1145x over previous
#include <cuda_runtime.h>

// Problem dimensions
static constexpr int NB = 512;   // batch
static constexpr int NT = 512;   // time
static constexpr int NOBS = 64;  // obs dim
static constexpr int NH = 256;   // hidden
static constexpr int NG = 1024;  // 4*H
static constexpr int NLAT = 16;  // latent
static constexpr int NBLK = 128; // persistent grid

// ---------------- scratch (device globals; no allocation allowed) ----------
__device__ float g_xp[(size_t)NT * NB * NH];   // [t*NB + sorted_b][h]
__device__ float g_Wr_ie[NH * NG];             // Wi_e reordered: [k][4j+g]
__device__ float g_Wr_he[NH * NG];             // Wh_e reordered
__device__ float g_Wr_d[NH * NG];              // (Wi_d + Wh_d) reordered
__device__ float g_br_e[NG];                   // b_e reordered
__device__ float g_br_d[NG];                   // b_d reordered
__device__ float g_h[2][NB * NH];              // ping-pong hidden state (sorted order)
__device__ int   g_len[NB];                    // per-row valid length (original order)
__device__ int   g_pos[NB];                    // original b -> sorted position
__device__ int   g_perm[NB];                   // sorted position -> original b
__device__ int   g_lens[NB];                   // lengths in sorted (descending) order
__device__ unsigned g_flag[16][16 * 32];       // per-(group,block) step flags, 128B stride

// ---------------- helpers ---------------------------------------------------
union F2U { unsigned long long u; float f[2]; };

__device__ __forceinline__ void fma2(unsigned long long& d, unsigned long long a,
                                     unsigned long long b) {
    asm("fma.rn.f32x2 %0, %1, %2, %0;" : "+l"(d) : "l"(a), "l"(b));
}

__device__ __forceinline__ unsigned long long dupr(float x) {
    unsigned long long r;
    asm("mov.b64 %0, {%1, %1};" : "=l"(r) : "f"(x));
    return r;
}

__device__ __forceinline__ float fsig(float x) {
    return __fdividef(1.0f, 1.0f + __expf(-x));
}
__device__ __forceinline__ float ftanh(float x) {
    return 1.0f - __fdividef(2.0f, __expf(2.0f * x) + 1.0f);
}

__device__ __forceinline__ void barj(int barid) {
    asm volatile("bar.sync %0, 256;" :: "r"(barid) : "memory");
}

__device__ __forceinline__ void flag_signal(int g, int myslot, unsigned target) {
    asm volatile("st.release.gpu.global.b32 [%0], %1;"
                 :: "l"(&g_flag[g][myslot * 32]), "r"(target) : "memory");
}

__device__ __forceinline__ void flag_wait(int g, unsigned target) {
    const int lane = threadIdx.x & 31;
    if (lane < 16) {
        unsigned cur;
        do {
            asm volatile("ld.acquire.gpu.global.b32 %0, [%1];"
                         : "=r"(cur) : "l"(&g_flag[g][lane * 32]) : "memory");
        } while ((int)(cur - target) < 0);
    }
    __syncwarp();
}

// ---------------- setup: weight reorder + mask lengths + flag reset ----------
__global__ void k_setup(const void* __restrict__ mask,
                        const float* __restrict__ Wi_e, const float* __restrict__ Wh_e,
                        const float* __restrict__ Wi_d, const float* __restrict__ Wh_d,
                        const float* __restrict__ b_e, const float* __restrict__ b_d) {
    const int idx = blockIdx.x * 256 + threadIdx.x;   // grid 1024 x 256 = NH*NG
    {
        int k = idx >> 10, c = idx & 1023;
        int g = c & 3, j = c >> 2;
        int src = k * NG + g * NH + j;
        g_Wr_ie[idx] = Wi_e[src];
        g_Wr_he[idx] = Wh_e[src];
        g_Wr_d[idx]  = Wi_d[src] + Wh_d[src];   // decoder input == hidden -> fold
    }
    if (idx < NG) {
        int g = idx & 3, j = idx >> 2;
        g_br_e[idx] = b_e[g * NH + j];
        g_br_d[idx] = b_d[g * NH + j];
    }
    if (idx < 16 * 16 * 32) ((unsigned*)g_flag)[idx] = 0u;
    if (blockIdx.x < NB) {
        const int b = blockIdx.x, tid = threadIdx.x;
        const bool u8 = (((const int*)mask)[0] != 1);
        int cnt = 0;
        for (int t = tid; t < NT; t += 256)
            cnt += u8 ? (((const unsigned char*)mask)[(size_t)b * NT + t] != 0)
                      : (((const int*)mask)[(size_t)b * NT + t] != 0);
#pragma unroll
        for (int off = 16; off; off >>= 1) cnt += __shfl_xor_sync(0xffffffffu, cnt, off);
        __shared__ int sred[8];
        if ((tid & 31) == 0) sred[tid >> 5] = cnt;
        __syncthreads();
        if (tid == 0) {
            int s = 0;
#pragma unroll
            for (int i = 0; i < 8; i++) s += sred[i];
            g_len[b] = s;
        }
    }
}

// ---------------- sort rows by length (descending), stable -------------------
__global__ void __launch_bounds__(NB) k_sort() {
    __shared__ int slen[NB];
    const int b = threadIdx.x;
    slen[b] = g_len[b];
    __syncthreads();
    const int L = slen[b];
    int rank = 0;
    for (int q = 0; q < NB; q++) {
        int Lq = slen[q];
        rank += (Lq > L) || (Lq == L && q < b);
    }
    g_pos[b] = rank;
    g_perm[rank] = b;
    g_lens[rank] = L;
}

// ---------------- K1: input projection  xp = leaky(x @ Wip + bip) -----------
// Writes xp in SORTED row order: g_xp[t*NB + pos[b]].
__global__ void __launch_bounds__(256) k_inproj(const float* __restrict__ x,
                                                const float* __restrict__ Wip,
                                                const float* __restrict__ bip) {
    __shared__ __align__(16) float sA[16][64];
    __shared__ __align__(16) float sB[16][64];
    const int tid = threadIdx.x;
    const int r0 = blockIdx.x * 64, c0 = blockIdx.y * 64;
    const int tx = tid & 15, ty = tid >> 4;
    const int am = tid >> 2, ak = (tid & 3) * 4;
    const int bk = tid >> 4, bc = (tid & 15) * 4;
    float acc[4][4] = {};
    for (int k0 = 0; k0 < NOBS; k0 += 16) {
        int r = r0 + am;
        int t = r >> 9;
        int b = r & (NB - 1);
        float4 av = *reinterpret_cast<const float4*>(&x[((size_t)b * NT + t) * NOBS + k0 + ak]);
        sA[ak + 0][am] = av.x; sA[ak + 1][am] = av.y;
        sA[ak + 2][am] = av.z; sA[ak + 3][am] = av.w;
        float4 bv = *reinterpret_cast<const float4*>(&Wip[(size_t)(k0 + bk) * NH + c0 + bc]);
        *reinterpret_cast<float4*>(&sB[bk][bc]) = bv;
        __syncthreads();
#pragma unroll
        for (int kk = 0; kk < 16; kk++) {
            float4 a4 = *reinterpret_cast<const float4*>(&sA[kk][ty * 4]);
            float4 b4 = *reinterpret_cast<const float4*>(&sB[kk][tx * 4]);
            float ar[4] = {a4.x, a4.y, a4.z, a4.w};
            float br[4] = {b4.x, b4.y, b4.z, b4.w};
#pragma unroll
            for (int i = 0; i < 4; i++)
#pragma unroll
                for (int jj = 0; jj < 4; jj++)
                    acc[i][jj] += ar[i] * br[jj];
        }
        __syncthreads();
    }
#pragma unroll
    for (int i = 0; i < 4; i++) {
        int r = r0 + ty * 4 + i;
        int t = r >> 9;
        int b = r & (NB - 1);
        size_t wr = (size_t)t * NB + g_pos[b];
        float4 v;
        float z0 = acc[i][0] + bip[c0 + tx * 4 + 0];
        float z1 = acc[i][1] + bip[c0 + tx * 4 + 1];
        float z2 = acc[i][2] + bip[c0 + tx * 4 + 2];
        float z3 = acc[i][3] + bip[c0 + tx * 4 + 3];
        v.x = z0 > 0.0f ? z0 : 0.01f * z0;
        v.y = z1 > 0.0f ? z1 : 0.01f * z1;
        v.z = z2 > 0.0f ? z2 : 0.01f * z2;
        v.w = z3 > 0.0f ? z3 : 0.01f * z3;
        *reinterpret_cast<float4*>(&g_xp[wr * NH + c0 + tx * 4]) = v;
    }
}

// ---------------- encoder scan: fused x-GEMM + length-sorted early exit ------
// Rows are in sorted (descending length) order; group g = sorted rows
// [32g, 32g+32) stops at TG = g_lens[32g] (its max length). Exact: rows with
// shorter len do masked updates until TG, identical to the full run; steps
// beyond TG only produced discarded values. Final h copied to buffer 0.
__global__ void __launch_bounds__(512, 1) k_escan() {
    extern __shared__ float sm[];
    float* sWh = sm;                       // [256 k][64]  Wh_e tile   64 KB
    float* sWi = sWh + NH * 64;            // [256 k][64]  Wi_e tile   64 KB
    float* sA  = sWi + NH * 64;            // 2 x [256 k][32 rows]     64 KB
    float* sR  = sA + 2 * NH * 32;         // 2 x [16][128] partials   16 KB

    const int tid  = threadIdx.x;
    const int jid  = tid >> 8;
    const int jtid = tid & 255;
    const int barid = 1 + jid;
    const int by = blockIdx.x >> 3;
    const int g  = (blockIdx.x & 7) + jid * 8;
    const int b0 = g * 32;
    const int c0 = by * 64;
    const int sub = jtid & 127;
    const int kb  = (jtid >> 7) * 128;
    const int tx = sub & 15, ty = sub >> 4;
    const int j  = (c0 >> 2) + tx;
    const int sr  = jtid & 31;
    const int sk0 = (jtid >> 5) * 32;
    float* sAj = sA + jid * NH * 32;
    float* sRj = sR + jid * 16 * 128;
    const bool lower = (jtid < 128);
    const int TG = g_lens[b0];             // group max length (descending sort)

    for (int q = tid; q < NH * 16; q += 512) {
        int k = q >> 4, cc = (q & 15) * 4;
        *reinterpret_cast<float4*>(&sWh[k * 64 + cc]) =
            *reinterpret_cast<const float4*>(&g_Wr_he[(size_t)k * NG + c0 + cc]);
        *reinterpret_cast<float4*>(&sWi[k * 64 + cc]) =
            *reinterpret_cast<const float4*>(&g_Wr_ie[(size_t)k * NG + c0 + cc]);
    }
    const float4 bv = *reinterpret_cast<const float4*>(&g_br_e[c0 + tx * 4]);

    float rc[4], rh[4];
    int rlen[4];
#pragma unroll
    for (int i = 0; i < 4; i++) {
        const int b = b0 + ty * 4 + i;
        rc[i] = 0.0f; rh[i] = 0.0f; rlen[i] = g_lens[b];
        if (lower) g_h[0][b * NH + j] = 0.0f;
    }
    __syncthreads();
    if (jtid == 0) flag_signal(g, by, 1u);

    F2U acc[4][2];

    // ---- prologue: zx for step 0 ----
    {
        float4 tmp[8];
#pragma unroll
        for (int i = 0; i < 8; i++)
            tmp[i] = *reinterpret_cast<const float4*>(
                &g_xp[(size_t)(b0 + sr) * NH + sk0 + 4 * i]);
#pragma unroll
        for (int i = 0; i < 8; i++) {
            sAj[(sk0 + 4 * i + 0) * 32 + sr] = tmp[i].x;
            sAj[(sk0 + 4 * i + 1) * 32 + sr] = tmp[i].y;
            sAj[(sk0 + 4 * i + 2) * 32 + sr] = tmp[i].z;
            sAj[(sk0 + 4 * i + 3) * 32 + sr] = tmp[i].w;
        }
    }
    barj(barid);
#pragma unroll
    for (int i = 0; i < 4; i++) {
        if (kb == 0) {
            acc[i][0].f[0] = bv.x; acc[i][0].f[1] = bv.y;
            acc[i][1].f[0] = bv.z; acc[i][1].f[1] = bv.w;
        } else { acc[i][0].u = 0ull; acc[i][1].u = 0ull; }
    }
    {
        float4 a_cur = *reinterpret_cast<const float4*>(&sAj[kb * 32 + ty * 4]);
        ulonglong2 b_cur = *reinterpret_cast<const ulonglong2*>(&sWi[kb * 64 + tx * 4]);
#pragma unroll 8
        for (int k = kb; k < kb + 127; k++) {
            float4 a_nxt = *reinterpret_cast<const float4*>(&sAj[(k + 1) * 32 + ty * 4]);
            ulonglong2 b_nxt = *reinterpret_cast<const ulonglong2*>(&sWi[(k + 1) * 64 + tx * 4]);
            unsigned long long a0 = dupr(a_cur.x), a1 = dupr(a_cur.y);
            unsigned long long a2 = dupr(a_cur.z), a3 = dupr(a_cur.w);
            fma2(acc[0][0].u, a0, b_cur.x); fma2(acc[0][1].u, a0, b_cur.y);
            fma2(acc[1][0].u, a1, b_cur.x); fma2(acc[1][1].u, a1, b_cur.y);
            fma2(acc[2][0].u, a2, b_cur.x); fma2(acc[2][1].u, a2, b_cur.y);
            fma2(acc[3][0].u, a3, b_cur.x); fma2(acc[3][1].u, a3, b_cur.y);
            a_cur = a_nxt; b_cur = b_nxt;
        }
        unsigned long long a0 = dupr(a_cur.x), a1 = dupr(a_cur.y);
        unsigned long long a2 = dupr(a_cur.z), a3 = dupr(a_cur.w);
        fma2(acc[0][0].u, a0, b_cur.x); fma2(acc[0][1].u, a0, b_cur.y);
        fma2(acc[1][0].u, a1, b_cur.x); fma2(acc[1][1].u, a1, b_cur.y);
        fma2(acc[2][0].u, a2, b_cur.x); fma2(acc[2][1].u, a2, b_cur.y);
        fma2(acc[3][0].u, a3, b_cur.x); fma2(acc[3][1].u, a3, b_cur.y);
    }
    barj(barid);
    flag_wait(g, 1u);

    for (int t = 0; t < TG; t++) {
        const float* __restrict__ h_in = g_h[t & 1];
        float* __restrict__ h_out = g_h[(t & 1) ^ 1];

        // ---- stage h[t] tile ----
        {
            float4 tmp[8];
#pragma unroll
            for (int i = 0; i < 8; i++)
                tmp[i] = *reinterpret_cast<const float4*>(
                    &h_in[(size_t)(b0 + sr) * NH + sk0 + 4 * i]);
#pragma unroll
            for (int i = 0; i < 8; i++) {
                sAj[(sk0 + 4 * i + 0) * 32 + sr] = tmp[i].x;
                sAj[(sk0 + 4 * i + 1) * 32 + sr] = tmp[i].y;
                sAj[(sk0 + 4 * i + 2) * 32 + sr] = tmp[i].z;
                sAj[(sk0 + 4 * i + 3) * 32 + sr] = tmp[i].w;
            }
        }
        barj(barid);

        // ---- h-GEMM accumulating onto zx partials ----
        {
            float4 a_cur = *reinterpret_cast<const float4*>(&sAj[kb * 32 + ty * 4]);
            ulonglong2 b_cur = *reinterpret_cast<const ulonglong2*>(&sWh[kb * 64 + tx * 4]);
#pragma unroll 8
            for (int k = kb; k < kb + 127; k++) {
                float4 a_nxt = *reinterpret_cast<const float4*>(&sAj[(k + 1) * 32 + ty * 4]);
                ulonglong2 b_nxt = *reinterpret_cast<const ulonglong2*>(&sWh[(k + 1) * 64 + tx * 4]);
                unsigned long long a0 = dupr(a_cur.x), a1 = dupr(a_cur.y);
                unsigned long long a2 = dupr(a_cur.z), a3 = dupr(a_cur.w);
                fma2(acc[0][0].u, a0, b_cur.x); fma2(acc[0][1].u, a0, b_cur.y);
                fma2(acc[1][0].u, a1, b_cur.x); fma2(acc[1][1].u, a1, b_cur.y);
                fma2(acc[2][0].u, a2, b_cur.x); fma2(acc[2][1].u, a2, b_cur.y);
                fma2(acc[3][0].u, a3, b_cur.x); fma2(acc[3][1].u, a3, b_cur.y);
                a_cur = a_nxt; b_cur = b_nxt;
            }
            unsigned long long a0 = dupr(a_cur.x), a1 = dupr(a_cur.y);
            unsigned long long a2 = dupr(a_cur.z), a3 = dupr(a_cur.w);
            fma2(acc[0][0].u, a0, b_cur.x); fma2(acc[0][1].u, a0, b_cur.y);
            fma2(acc[1][0].u, a1, b_cur.x); fma2(acc[1][1].u, a1, b_cur.y);
            fma2(acc[2][0].u, a2, b_cur.x); fma2(acc[2][1].u, a2, b_cur.y);
            fma2(acc[3][0].u, a3, b_cur.x); fma2(acc[3][1].u, a3, b_cur.y);
        }

        if (!lower) {
#pragma unroll
            for (int i = 0; i < 4; i++) {
                sRj[(i * 4 + 0) * 128 + sub] = acc[i][0].f[0];
                sRj[(i * 4 + 1) * 128 + sub] = acc[i][0].f[1];
                sRj[(i * 4 + 2) * 128 + sub] = acc[i][1].f[0];
                sRj[(i * 4 + 3) * 128 + sub] = acc[i][1].f[1];
            }
        }
        barj(barid);

        if (lower) {
#pragma unroll
            for (int i = 0; i < 4; i++) {
                const int b = b0 + ty * 4 + i;
                float zi = acc[i][0].f[0] + sRj[(i * 4 + 0) * 128 + sub];
                float zf = acc[i][0].f[1] + sRj[(i * 4 + 1) * 128 + sub];
                float zg = acc[i][1].f[0] + sRj[(i * 4 + 2) * 128 + sub];
                float zo = acc[i][1].f[1] + sRj[(i * 4 + 3) * 128 + sub];
                float ig = fsig(zi), fg = fsig(zf), gg = ftanh(zg), og = fsig(zo);
                float nc = fg * rc[i] + ig * gg;
                float nh = og * ftanh(nc);
                bool m = (t < rlen[i]);
                rc[i] = m ? nc : rc[i];
                rh[i] = m ? nh : rh[i];
                h_out[b * NH + j] = rh[i];
            }
        }
        barj(barid);
        if (t + 1 < TG) {
            if (jtid == 0) flag_signal(g, by, (unsigned)(t + 2));

            // ---- stage xp[t+1] and run x-GEMM in the wait window ----
            {
                float4 tmp[8];
#pragma unroll
                for (int i = 0; i < 8; i++)
                    tmp[i] = *reinterpret_cast<const float4*>(
                        &g_xp[((size_t)(t + 1) * NB + b0 + sr) * NH + sk0 + 4 * i]);
#pragma unroll
                for (int i = 0; i < 8; i++) {
                    sAj[(sk0 + 4 * i + 0) * 32 + sr] = tmp[i].x;
                    sAj[(sk0 + 4 * i + 1) * 32 + sr] = tmp[i].y;
                    sAj[(sk0 + 4 * i + 2) * 32 + sr] = tmp[i].z;
                    sAj[(sk0 + 4 * i + 3) * 32 + sr] = tmp[i].w;
                }
            }
            barj(barid);
#pragma unroll
            for (int i = 0; i < 4; i++) {
                if (kb == 0) {
                    acc[i][0].f[0] = bv.x; acc[i][0].f[1] = bv.y;
                    acc[i][1].f[0] = bv.z; acc[i][1].f[1] = bv.w;
                } else { acc[i][0].u = 0ull; acc[i][1].u = 0ull; }
            }
            {
                float4 a_cur = *reinterpret_cast<const float4*>(&sAj[kb * 32 + ty * 4]);
                ulonglong2 b_cur = *reinterpret_cast<const ulonglong2*>(&sWi[kb * 64 + tx * 4]);
#pragma unroll 8
                for (int k = kb; k < kb + 127; k++) {
                    float4 a_nxt = *reinterpret_cast<const float4*>(&sAj[(k + 1) * 32 + ty * 4]);
                    ulonglong2 b_nxt = *reinterpret_cast<const ulonglong2*>(&sWi[(k + 1) * 64 + tx * 4]);
                    unsigned long long a0 = dupr(a_cur.x), a1 = dupr(a_cur.y);
                    unsigned long long a2 = dupr(a_cur.z), a3 = dupr(a_cur.w);
                    fma2(acc[0][0].u, a0, b_cur.x); fma2(acc[0][1].u, a0, b_cur.y);
                    fma2(acc[1][0].u, a1, b_cur.x); fma2(acc[1][1].u, a1, b_cur.y);
                    fma2(acc[2][0].u, a2, b_cur.x); fma2(acc[2][1].u, a2, b_cur.y);
                    fma2(acc[3][0].u, a3, b_cur.x); fma2(acc[3][1].u, a3, b_cur.y);
                    a_cur = a_nxt; b_cur = b_nxt;
                }
                unsigned long long a0 = dupr(a_cur.x), a1 = dupr(a_cur.y);
                unsigned long long a2 = dupr(a_cur.z), a3 = dupr(a_cur.w);
                fma2(acc[0][0].u, a0, b_cur.x); fma2(acc[0][1].u, a0, b_cur.y);
                fma2(acc[1][0].u, a1, b_cur.x); fma2(acc[1][1].u, a1, b_cur.y);
                fma2(acc[2][0].u, a2, b_cur.x); fma2(acc[2][1].u, a2, b_cur.y);
                fma2(acc[3][0].u, a3, b_cur.x); fma2(acc[3][1].u, a3, b_cur.y);
            }
            barj(barid);
            flag_wait(g, (unsigned)(t + 2));
        }
    }

    // final h must end in buffer 0 for k_latctx (ping-pong parity varies per group)
    if ((TG & 1) && lower) {
#pragma unroll
        for (int i = 0; i < 4; i++)
            g_h[0][(b0 + ty * 4 + i) * NH + j] = rh[i];
    }
}

// ---------------- decoder scan (sorted rows; de-permute on store) ------------
__global__ void __launch_bounds__(512, 1) k_dscan(unsigned ebase,
                                                  const float* __restrict__ Wop,
                                                  const float* __restrict__ bop,
                                                  float* __restrict__ out) {
    extern __shared__ float sm[];
    float* sW  = sm;                       // [256 k][64]             64 KB
    float* sA  = sm + NH * 64;             // 2 x [256 k][32 rows]    64 KB
    float* sR  = sA + 2 * NH * 32;         // 2 x [16][128] partials  16 KB
    float* sRp = sR + 2 * 16 * 128;        // 2 x [128] pred partials  1 KB
    float* sP  = sRp + 2 * 128;            // [256 k][4] Wop tile      4 KB

    const int tid  = threadIdx.x;
    const int jid  = tid >> 8;
    const int jtid = tid & 255;
    const int barid = 1 + jid;
    const int by = blockIdx.x >> 3;
    const int g  = (blockIdx.x & 7) + jid * 8;
    const int b0 = g * 32;
    const int c0 = by * 64;
    const int sub = jtid & 127;
    const int kb  = (jtid >> 7) * 128;
    const int tx = sub & 15, ty = sub >> 4;
    const int j  = (c0 >> 2) + tx;
    const int pr = sub >> 2, pc = sub & 3;
    const int sr  = jtid & 31;
    const int sk0 = (jtid >> 5) * 32;
    float* sAj  = sA + jid * NH * 32;
    float* sRj  = sR + jid * 16 * 128;
    float* sRpj = sRp + jid * 128;
    const bool lower = (jtid < 128);
    const int ob = g_perm[b0 + pr];        // original row for recon stores

    for (int q = tid; q < NH * 16; q += 512) {
        int k = q >> 4, cc = (q & 15) * 4;
        *reinterpret_cast<float4*>(&sW[k * 64 + cc]) =
            *reinterpret_cast<const float4*>(&g_Wr_d[(size_t)k * NG + c0 + cc]);
    }
    for (int q = tid; q < NH * 4; q += 512)
        sP[q] = Wop[(q >> 2) * NOBS + by * 4 + (q & 3)];
    const float4 bv = *reinterpret_cast<const float4*>(&g_br_d[c0 + tx * 4]);
    const float bopv = bop[by * 4 + pc];

    float rc[4], rh[4];
#pragma unroll
    for (int i = 0; i < 4; i++) {
        const int b = b0 + ty * 4 + i;
        float v = g_h[0][b * NH + j];
        rc[i] = v; rh[i] = v;
    }
    __syncthreads();

    const int TEND = NT + 1;
    for (int t = 0; t < TEND; t++) {
        const float* __restrict__ h_in = g_h[t & 1];
        float* __restrict__ h_out = g_h[(t & 1) ^ 1];

        {
            float4 tmp[8];
#pragma unroll
            for (int i = 0; i < 8; i++)
                tmp[i] = *reinterpret_cast<const float4*>(
                    &h_in[(size_t)(b0 + sr) * NH + sk0 + 4 * i]);
#pragma unroll
            for (int i = 0; i < 8; i++) {
                sAj[(sk0 + 4 * i + 0) * 32 + sr] = tmp[i].x;
                sAj[(sk0 + 4 * i + 1) * 32 + sr] = tmp[i].y;
                sAj[(sk0 + 4 * i + 2) * 32 + sr] = tmp[i].z;
                sAj[(sk0 + 4 * i + 3) * 32 + sr] = tmp[i].w;
            }
        }
        barj(barid);

        F2U acc[4][2];
#pragma unroll
        for (int i = 0; i < 4; i++) { acc[i][0].u = 0ull; acc[i][1].u = 0ull; }
        float accp = 0.0f;

        float4 a_cur = *reinterpret_cast<const float4*>(&sAj[kb * 32 + ty * 4]);
        ulonglong2 b_cur = *reinterpret_cast<const ulonglong2*>(&sW[kb * 64 + tx * 4]);
        float p_cur = sAj[kb * 32 + pr], w_cur = sP[kb * 4 + pc];
#pragma unroll 8
        for (int k = kb; k < kb + 127; k++) {
            float4 a_nxt = *reinterpret_cast<const float4*>(&sAj[(k + 1) * 32 + ty * 4]);
            ulonglong2 b_nxt = *reinterpret_cast<const ulonglong2*>(&sW[(k + 1) * 64 + tx * 4]);
            float p_nxt = sAj[(k + 1) * 32 + pr], w_nxt = sP[(k + 1) * 4 + pc];
            unsigned long long a0 = dupr(a_cur.x), a1 = dupr(a_cur.y);
            unsigned long long a2 = dupr(a_cur.z), a3 = dupr(a_cur.w);
            fma2(acc[0][0].u, a0, b_cur.x); fma2(acc[0][1].u, a0, b_cur.y);
            fma2(acc[1][0].u, a1, b_cur.x); fma2(acc[1][1].u, a1, b_cur.y);
            fma2(acc[2][0].u, a2, b_cur.x); fma2(acc[2][1].u, a2, b_cur.y);
            fma2(acc[3][0].u, a3, b_cur.x); fma2(acc[3][1].u, a3, b_cur.y);
            accp = fmaf(p_cur, w_cur, accp);
            a_cur = a_nxt; b_cur = b_nxt; p_cur = p_nxt; w_cur = w_nxt;
        }
        {
            unsigned long long a0 = dupr(a_cur.x), a1 = dupr(a_cur.y);
            unsigned long long a2 = dupr(a_cur.z), a3 = dupr(a_cur.w);
            fma2(acc[0][0].u, a0, b_cur.x); fma2(acc[0][1].u, a0, b_cur.y);
            fma2(acc[1][0].u, a1, b_cur.x); fma2(acc[1][1].u, a1, b_cur.y);
            fma2(acc[2][0].u, a2, b_cur.x); fma2(acc[2][1].u, a2, b_cur.y);
            fma2(acc[3][0].u, a3, b_cur.x); fma2(acc[3][1].u, a3, b_cur.y);
            accp = fmaf(p_cur, w_cur, accp);
        }

        if (!lower) {
#pragma unroll
            for (int i = 0; i < 4; i++) {
                sRj[(i * 4 + 0) * 128 + sub] = acc[i][0].f[0];
                sRj[(i * 4 + 1) * 128 + sub] = acc[i][0].f[1];
                sRj[(i * 4 + 2) * 128 + sub] = acc[i][1].f[0];
                sRj[(i * 4 + 3) * 128 + sub] = acc[i][1].f[1];
            }
            sRpj[sub] = accp;
        }
        barj(barid);

        if (lower && t < NT) {
#pragma unroll
            for (int i = 0; i < 4; i++) {
                const int b = b0 + ty * 4 + i;
                float zi = acc[i][0].f[0] + sRj[(i * 4 + 0) * 128 + sub] + bv.x;
                float zf = acc[i][0].f[1] + sRj[(i * 4 + 1) * 128 + sub] + bv.y;
                float zg = acc[i][1].f[0] + sRj[(i * 4 + 2) * 128 + sub] + bv.z;
                float zo = acc[i][1].f[1] + sRj[(i * 4 + 3) * 128 + sub] + bv.w;
                float ig = fsig(zi), fg = fsig(zf), gg = ftanh(zg), og = fsig(zo);
                float nc = fg * rc[i] + ig * gg;
                float nh = og * ftanh(nc);
                rc[i] = nc; rh[i] = nh;
                h_out[b * NH + j] = nh;
            }
        }
        if (lower && t >= 1)
            out[((size_t)ob * NT + (t - 1)) * NOBS + by * 4 + pc] =
                accp + sRpj[sub] + bopv;

        if (t + 1 < TEND) {
            barj(barid);
            if (jtid == 0) flag_signal(g, by, ebase + (unsigned)(t + 1));
            flag_wait(g, ebase + (unsigned)(t + 1));
        }
    }
}

// ---------------- latent + context (fused; de-permute latent store) ----------
__global__ void k_latctx(const float* __restrict__ Wlp, const float* __restrict__ blp,
                         const float* __restrict__ Wle, const float* __restrict__ ble,
                         float* __restrict__ out) {
    __shared__ float slat[NLAT];
    const int b = blockIdx.x, tid = threadIdx.x;
    const int l = tid >> 4, sub = tid & 15;
    const float* h = g_h[0];
    float s = 0.0f;
    for (int k = sub; k < NH; k += 16) s += h[b * NH + k] * Wlp[k * NLAT + l];
#pragma unroll
    for (int off = 8; off; off >>= 1) s += __shfl_xor_sync(0xffffffffu, s, off);
    if (sub == 0) {
        float v = s + blp[l];
        slat[l] = v;
        out[(size_t)NB * NT * NOBS + (size_t)g_perm[b] * NLAT + l] = v;
    }
    __syncthreads();
    float s2 = ble[tid];
#pragma unroll
    for (int l2 = 0; l2 < NLAT; l2++) s2 += slat[l2] * Wle[l2 * NH + tid];
    g_h[0][b * NH + tid] = s2 > 0.0f ? s2 : 0.01f * s2;
}

// ---------------- driver -----------------------------------------------------
extern "C" void kernel_launch(void* const* d_in, const int* in_sizes, int n_in,
                              void* d_out, int out_size) {
    (void)in_sizes; (void)n_in; (void)out_size;
    const float* x    = (const float*)d_in[0];
    const void*  mask = d_in[1];
    const float* Wip  = (const float*)d_in[2];
    const float* bip  = (const float*)d_in[3];
    const float* Wi_e = (const float*)d_in[4];
    const float* Wh_e = (const float*)d_in[5];
    const float* b_e  = (const float*)d_in[6];
    const float* Wlp  = (const float*)d_in[7];
    const float* blp  = (const float*)d_in[8];
    const float* Wle  = (const float*)d_in[9];
    const float* ble  = (const float*)d_in[10];
    const float* Wi_d = (const float*)d_in[11];
    const float* Wh_d = (const float*)d_in[12];
    const float* b_d  = (const float*)d_in[13];
    const float* Wop  = (const float*)d_in[14];
    const float* bop  = (const float*)d_in[15];
    float* out = (float*)d_out;

    const size_t smem_e = (size_t)(NH * 64 * 2 + 2 * NH * 32 + 2 * 16 * 128) * sizeof(float);
    const size_t smem_d = (size_t)(NH * 64 + 2 * NH * 32 + 2 * 16 * 128 + 2 * 128 + NH * 4)
                          * sizeof(float);
    cudaFuncSetAttribute(k_escan, cudaFuncAttributeMaxDynamicSharedMemorySize, (int)smem_e);
    cudaFuncSetAttribute(k_dscan, cudaFuncAttributeMaxDynamicSharedMemorySize, (int)smem_d);

    // 6 graph nodes total
    k_setup<<<1024, 256>>>(mask, Wi_e, Wh_e, Wi_d, Wh_d, b_e, b_d);
    k_sort<<<1, NB>>>();
    k_inproj<<<dim3(NB * NT / 64, NH / 64), 256>>>(x, Wip, bip);
    k_escan<<<NBLK, 512, smem_e>>>();
    k_latctx<<<NB, 256>>>(Wlp, blp, Wle, ble, out);
    k_dscan<<<NBLK, 512, smem_d>>>(513u, Wop, bop, out);
}

// round 16
// speedup vs baseline: 1.4580x; 1.0274x over previous
#include <cuda_runtime.h>

// Problem dimensions
static constexpr int NB = 512;   // batch
static constexpr int NT = 512;   // time
static constexpr int NOBS = 64;  // obs dim
static constexpr int NH = 256;   // hidden
static constexpr int NG = 1024;  // 4*H
static constexpr int NLAT = 16;  // latent
static constexpr int NBLK = 128; // persistent grid

// ---------------- scratch (device globals; no allocation allowed) ----------
__device__ float g_xp[(size_t)NT * NB * NH];   // [t*NB + sorted_b][h]
__device__ float g_Wr_ie[NH * NG];             // Wi_e reordered: [k][4j+g]
__device__ float g_Wr_he[NH * NG];             // Wh_e reordered
__device__ float g_Wr_d[NH * NG];              // (Wi_d + Wh_d) reordered
__device__ float g_br_e[NG];                   // b_e reordered
__device__ float g_br_d[NG];                   // b_d reordered
__device__ float g_h[2][NB * NH];              // ping-pong hidden state (sorted order)
__device__ int   g_len[NB];                    // per-row valid length (original order)
__device__ int   g_pos[NB];                    // original b -> sorted position
__device__ int   g_perm[NB];                   // sorted position -> original b
__device__ int   g_lens[NB];                   // lengths in sorted (descending) order
__device__ unsigned g_flag[16][16 * 32];       // per-(group,block) step flags, 128B stride

// ---------------- helpers ---------------------------------------------------
union F2U { unsigned long long u; float f[2]; };

__device__ __forceinline__ void fma2(unsigned long long& d, unsigned long long a,
                                     unsigned long long b) {
    asm("fma.rn.f32x2 %0, %1, %2, %0;" : "+l"(d) : "l"(a), "l"(b));
}

__device__ __forceinline__ unsigned long long dupr(float x) {
    unsigned long long r;
    asm("mov.b64 %0, {%1, %1};" : "=l"(r) : "f"(x));
    return r;
}

__device__ __forceinline__ float fsig(float x) {
    return __fdividef(1.0f, 1.0f + __expf(-x));
}
__device__ __forceinline__ float ftanh(float x) {
    return 1.0f - __fdividef(2.0f, __expf(2.0f * x) + 1.0f);
}

__device__ __forceinline__ void barj(int barid) {
    asm volatile("bar.sync %0, 256;" :: "r"(barid) : "memory");
}

__device__ __forceinline__ void flag_signal(int g, int myslot, unsigned target) {
    asm volatile("st.release.gpu.global.b32 [%0], %1;"
                 :: "l"(&g_flag[g][myslot * 32]), "r"(target) : "memory");
}

__device__ __forceinline__ void flag_wait(int g, unsigned target) {
    const int lane = threadIdx.x & 31;
    if (lane < 16) {
        unsigned cur;
        do {
            asm volatile("ld.acquire.gpu.global.b32 %0, [%1];"
                         : "=r"(cur) : "l"(&g_flag[g][lane * 32]) : "memory");
        } while ((int)(cur - target) < 0);
    }
    __syncwarp();
}

// ---------------- setup: weight reorder + mask lengths + flag reset ----------
__global__ void k_setup(const void* __restrict__ mask,
                        const float* __restrict__ Wi_e, const float* __restrict__ Wh_e,
                        const float* __restrict__ Wi_d, const float* __restrict__ Wh_d,
                        const float* __restrict__ b_e, const float* __restrict__ b_d) {
    const int idx = blockIdx.x * 256 + threadIdx.x;   // grid 1024 x 256 = NH*NG
    {
        int k = idx >> 10, c = idx & 1023;
        int g = c & 3, j = c >> 2;
        int src = k * NG + g * NH + j;
        g_Wr_ie[idx] = Wi_e[src];
        g_Wr_he[idx] = Wh_e[src];
        g_Wr_d[idx]  = Wi_d[src] + Wh_d[src];   // decoder input == hidden -> fold
    }
    if (idx < NG) {
        int g = idx & 3, j = idx >> 2;
        g_br_e[idx] = b_e[g * NH + j];
        g_br_d[idx] = b_d[g * NH + j];
    }
    if (idx < 16 * 16 * 32) ((unsigned*)g_flag)[idx] = 0u;
    if (blockIdx.x < NB) {
        const int b = blockIdx.x, tid = threadIdx.x;
        const bool u8 = (((const int*)mask)[0] != 1);
        int cnt = 0;
        for (int t = tid; t < NT; t += 256)
            cnt += u8 ? (((const unsigned char*)mask)[(size_t)b * NT + t] != 0)
                      : (((const int*)mask)[(size_t)b * NT + t] != 0);
#pragma unroll
        for (int off = 16; off; off >>= 1) cnt += __shfl_xor_sync(0xffffffffu, cnt, off);
        __shared__ int sred[8];
        if ((tid & 31) == 0) sred[tid >> 5] = cnt;
        __syncthreads();
        if (tid == 0) {
            int s = 0;
#pragma unroll
            for (int i = 0; i < 8; i++) s += sred[i];
            g_len[b] = s;
        }
    }
}

// ---------------- sort rows by length (descending), stable -------------------
__global__ void __launch_bounds__(NB) k_sort() {
    __shared__ int slen[NB];
    const int b = threadIdx.x;
    slen[b] = g_len[b];
    __syncthreads();
    const int L = slen[b];
    int rank = 0;
    for (int q = 0; q < NB; q++) {
        int Lq = slen[q];
        rank += (Lq > L) || (Lq == L && q < b);
    }
    g_pos[b] = rank;
    g_perm[rank] = b;
    g_lens[rank] = L;
}

// ---------------- K1: input projection  xp = leaky(x @ Wip + bip) -----------
// Writes xp in SORTED row order: g_xp[t*NB + pos[b]].
__global__ void __launch_bounds__(256) k_inproj(const float* __restrict__ x,
                                                const float* __restrict__ Wip,
                                                const float* __restrict__ bip) {
    __shared__ __align__(16) float sA[16][64];
    __shared__ __align__(16) float sB[16][64];
    const int tid = threadIdx.x;
    const int r0 = blockIdx.x * 64, c0 = blockIdx.y * 64;
    const int tx = tid & 15, ty = tid >> 4;
    const int am = tid >> 2, ak = (tid & 3) * 4;
    const int bk = tid >> 4, bc = (tid & 15) * 4;
    float acc[4][4] = {};
    for (int k0 = 0; k0 < NOBS; k0 += 16) {
        int r = r0 + am;
        int t = r >> 9;
        int b = r & (NB - 1);
        float4 av = *reinterpret_cast<const float4*>(&x[((size_t)b * NT + t) * NOBS + k0 + ak]);
        sA[ak + 0][am] = av.x; sA[ak + 1][am] = av.y;
        sA[ak + 2][am] = av.z; sA[ak + 3][am] = av.w;
        float4 bv = *reinterpret_cast<const float4*>(&Wip[(size_t)(k0 + bk) * NH + c0 + bc]);
        *reinterpret_cast<float4*>(&sB[bk][bc]) = bv;
        __syncthreads();
#pragma unroll
        for (int kk = 0; kk < 16; kk++) {
            float4 a4 = *reinterpret_cast<const float4*>(&sA[kk][ty * 4]);
            float4 b4 = *reinterpret_cast<const float4*>(&sB[kk][tx * 4]);
            float ar[4] = {a4.x, a4.y, a4.z, a4.w};
            float br[4] = {b4.x, b4.y, b4.z, b4.w};
#pragma unroll
            for (int i = 0; i < 4; i++)
#pragma unroll
                for (int jj = 0; jj < 4; jj++)
                    acc[i][jj] += ar[i] * br[jj];
        }
        __syncthreads();
    }
#pragma unroll
    for (int i = 0; i < 4; i++) {
        int r = r0 + ty * 4 + i;
        int t = r >> 9;
        int b = r & (NB - 1);
        size_t wr = (size_t)t * NB + g_pos[b];
        float4 v;
        float z0 = acc[i][0] + bip[c0 + tx * 4 + 0];
        float z1 = acc[i][1] + bip[c0 + tx * 4 + 1];
        float z2 = acc[i][2] + bip[c0 + tx * 4 + 2];
        float z3 = acc[i][3] + bip[c0 + tx * 4 + 3];
        v.x = z0 > 0.0f ? z0 : 0.01f * z0;
        v.y = z1 > 0.0f ? z1 : 0.01f * z1;
        v.z = z2 > 0.0f ? z2 : 0.01f * z2;
        v.w = z3 > 0.0f ? z3 : 0.01f * z3;
        *reinterpret_cast<float4*>(&g_xp[wr * NH + c0 + tx * 4]) = v;
    }
}

// ---------------- encoder scan: fused x-GEMM + length-sorted early exit ------
__global__ void __launch_bounds__(512, 1) k_escan() {
    extern __shared__ float sm[];
    float* sWh = sm;                       // [256 k][64]  Wh_e tile   64 KB
    float* sWi = sWh + NH * 64;            // [256 k][64]  Wi_e tile   64 KB
    float* sA  = sWi + NH * 64;            // 2 x [256 k][32 rows]     64 KB
    float* sR  = sA + 2 * NH * 32;         // 2 x [16][128] partials   16 KB

    const int tid  = threadIdx.x;
    const int jid  = tid >> 8;
    const int jtid = tid & 255;
    const int barid = 1 + jid;
    const int by = blockIdx.x >> 3;
    const int g  = (blockIdx.x & 7) + jid * 8;
    const int b0 = g * 32;
    const int c0 = by * 64;
    const int sub = jtid & 127;
    const int kb  = (jtid >> 7) * 128;
    const int tx = sub & 15, ty = sub >> 4;
    const int j  = (c0 >> 2) + tx;
    const int sr  = jtid & 31;
    const int sk0 = (jtid >> 5) * 32;
    float* sAj = sA + jid * NH * 32;
    float* sRj = sR + jid * 16 * 128;
    const bool lower = (jtid < 128);
    const int TG = g_lens[b0];             // group max length (descending sort)

    for (int q = tid; q < NH * 16; q += 512) {
        int k = q >> 4, cc = (q & 15) * 4;
        *reinterpret_cast<float4*>(&sWh[k * 64 + cc]) =
            *reinterpret_cast<const float4*>(&g_Wr_he[(size_t)k * NG + c0 + cc]);
        *reinterpret_cast<float4*>(&sWi[k * 64 + cc]) =
            *reinterpret_cast<const float4*>(&g_Wr_ie[(size_t)k * NG + c0 + cc]);
    }
    const float4 bv = *reinterpret_cast<const float4*>(&g_br_e[c0 + tx * 4]);

    float rc[4], rh[4];
    int rlen[4];
#pragma unroll
    for (int i = 0; i < 4; i++) {
        const int b = b0 + ty * 4 + i;
        rc[i] = 0.0f; rh[i] = 0.0f; rlen[i] = g_lens[b];
        if (lower) g_h[0][b * NH + j] = 0.0f;
    }
    __syncthreads();
    if (jtid == 0) flag_signal(g, by, 1u);

    F2U acc[4][2];

    // ---- prologue: zx for step 0 ----
    {
        float4 tmp[8];
#pragma unroll
        for (int i = 0; i < 8; i++)
            tmp[i] = *reinterpret_cast<const float4*>(
                &g_xp[(size_t)(b0 + sr) * NH + sk0 + 4 * i]);
#pragma unroll
        for (int i = 0; i < 8; i++) {
            sAj[(sk0 + 4 * i + 0) * 32 + sr] = tmp[i].x;
            sAj[(sk0 + 4 * i + 1) * 32 + sr] = tmp[i].y;
            sAj[(sk0 + 4 * i + 2) * 32 + sr] = tmp[i].z;
            sAj[(sk0 + 4 * i + 3) * 32 + sr] = tmp[i].w;
        }
    }
    barj(barid);
#pragma unroll
    for (int i = 0; i < 4; i++) {
        if (kb == 0) {
            acc[i][0].f[0] = bv.x; acc[i][0].f[1] = bv.y;
            acc[i][1].f[0] = bv.z; acc[i][1].f[1] = bv.w;
        } else { acc[i][0].u = 0ull; acc[i][1].u = 0ull; }
    }
    {
        float4 a_cur = *reinterpret_cast<const float4*>(&sAj[kb * 32 + ty * 4]);
        ulonglong2 b_cur = *reinterpret_cast<const ulonglong2*>(&sWi[kb * 64 + tx * 4]);
#pragma unroll 8
        for (int k = kb; k < kb + 127; k++) {
            float4 a_nxt = *reinterpret_cast<const float4*>(&sAj[(k + 1) * 32 + ty * 4]);
            ulonglong2 b_nxt = *reinterpret_cast<const ulonglong2*>(&sWi[(k + 1) * 64 + tx * 4]);
            unsigned long long a0 = dupr(a_cur.x), a1 = dupr(a_cur.y);
            unsigned long long a2 = dupr(a_cur.z), a3 = dupr(a_cur.w);
            fma2(acc[0][0].u, a0, b_cur.x); fma2(acc[0][1].u, a0, b_cur.y);
            fma2(acc[1][0].u, a1, b_cur.x); fma2(acc[1][1].u, a1, b_cur.y);
            fma2(acc[2][0].u, a2, b_cur.x); fma2(acc[2][1].u, a2, b_cur.y);
            fma2(acc[3][0].u, a3, b_cur.x); fma2(acc[3][1].u, a3, b_cur.y);
            a_cur = a_nxt; b_cur = b_nxt;
        }
        unsigned long long a0 = dupr(a_cur.x), a1 = dupr(a_cur.y);
        unsigned long long a2 = dupr(a_cur.z), a3 = dupr(a_cur.w);
        fma2(acc[0][0].u, a0, b_cur.x); fma2(acc[0][1].u, a0, b_cur.y);
        fma2(acc[1][0].u, a1, b_cur.x); fma2(acc[1][1].u, a1, b_cur.y);
        fma2(acc[2][0].u, a2, b_cur.x); fma2(acc[2][1].u, a2, b_cur.y);
        fma2(acc[3][0].u, a3, b_cur.x); fma2(acc[3][1].u, a3, b_cur.y);
    }
    barj(barid);
    flag_wait(g, 1u);

    for (int t = 0; t < TG; t++) {
        const float* __restrict__ h_in = g_h[t & 1];
        float* __restrict__ h_out = g_h[(t & 1) ^ 1];

        // ---- stage h[t] tile ----
        {
            float4 tmp[8];
#pragma unroll
            for (int i = 0; i < 8; i++)
                tmp[i] = *reinterpret_cast<const float4*>(
                    &h_in[(size_t)(b0 + sr) * NH + sk0 + 4 * i]);
#pragma unroll
            for (int i = 0; i < 8; i++) {
                sAj[(sk0 + 4 * i + 0) * 32 + sr] = tmp[i].x;
                sAj[(sk0 + 4 * i + 1) * 32 + sr] = tmp[i].y;
                sAj[(sk0 + 4 * i + 2) * 32 + sr] = tmp[i].z;
                sAj[(sk0 + 4 * i + 3) * 32 + sr] = tmp[i].w;
            }
        }
        barj(barid);

        // ---- h-GEMM accumulating onto zx partials ----
        {
            float4 a_cur = *reinterpret_cast<const float4*>(&sAj[kb * 32 + ty * 4]);
            ulonglong2 b_cur = *reinterpret_cast<const ulonglong2*>(&sWh[kb * 64 + tx * 4]);
#pragma unroll 8
            for (int k = kb; k < kb + 127; k++) {
                float4 a_nxt = *reinterpret_cast<const float4*>(&sAj[(k + 1) * 32 + ty * 4]);
                ulonglong2 b_nxt = *reinterpret_cast<const ulonglong2*>(&sWh[(k + 1) * 64 + tx * 4]);
                unsigned long long a0 = dupr(a_cur.x), a1 = dupr(a_cur.y);
                unsigned long long a2 = dupr(a_cur.z), a3 = dupr(a_cur.w);
                fma2(acc[0][0].u, a0, b_cur.x); fma2(acc[0][1].u, a0, b_cur.y);
                fma2(acc[1][0].u, a1, b_cur.x); fma2(acc[1][1].u, a1, b_cur.y);
                fma2(acc[2][0].u, a2, b_cur.x); fma2(acc[2][1].u, a2, b_cur.y);
                fma2(acc[3][0].u, a3, b_cur.x); fma2(acc[3][1].u, a3, b_cur.y);
                a_cur = a_nxt; b_cur = b_nxt;
            }
            unsigned long long a0 = dupr(a_cur.x), a1 = dupr(a_cur.y);
            unsigned long long a2 = dupr(a_cur.z), a3 = dupr(a_cur.w);
            fma2(acc[0][0].u, a0, b_cur.x); fma2(acc[0][1].u, a0, b_cur.y);
            fma2(acc[1][0].u, a1, b_cur.x); fma2(acc[1][1].u, a1, b_cur.y);
            fma2(acc[2][0].u, a2, b_cur.x); fma2(acc[2][1].u, a2, b_cur.y);
            fma2(acc[3][0].u, a3, b_cur.x); fma2(acc[3][1].u, a3, b_cur.y);
        }

        if (!lower) {
#pragma unroll
            for (int i = 0; i < 4; i++) {
                sRj[(i * 4 + 0) * 128 + sub] = acc[i][0].f[0];
                sRj[(i * 4 + 1) * 128 + sub] = acc[i][0].f[1];
                sRj[(i * 4 + 2) * 128 + sub] = acc[i][1].f[0];
                sRj[(i * 4 + 3) * 128 + sub] = acc[i][1].f[1];
            }
        }
        barj(barid);

        if (lower) {
#pragma unroll
            for (int i = 0; i < 4; i++) {
                const int b = b0 + ty * 4 + i;
                float zi = acc[i][0].f[0] + sRj[(i * 4 + 0) * 128 + sub];
                float zf = acc[i][0].f[1] + sRj[(i * 4 + 1) * 128 + sub];
                float zg = acc[i][1].f[0] + sRj[(i * 4 + 2) * 128 + sub];
                float zo = acc[i][1].f[1] + sRj[(i * 4 + 3) * 128 + sub];
                float ig = fsig(zi), fg = fsig(zf), gg = ftanh(zg), og = fsig(zo);
                float nc = fg * rc[i] + ig * gg;
                float nh = og * ftanh(nc);
                bool m = (t < rlen[i]);
                rc[i] = m ? nc : rc[i];
                rh[i] = m ? nh : rh[i];
                h_out[b * NH + j] = rh[i];
            }
        }
        barj(barid);
        if (t + 1 < TG) {
            if (jtid == 0) flag_signal(g, by, (unsigned)(t + 2));

            // ---- stage xp[t+1] and run x-GEMM in the wait window ----
            {
                float4 tmp[8];
#pragma unroll
                for (int i = 0; i < 8; i++)
                    tmp[i] = *reinterpret_cast<const float4*>(
                        &g_xp[((size_t)(t + 1) * NB + b0 + sr) * NH + sk0 + 4 * i]);
#pragma unroll
                for (int i = 0; i < 8; i++) {
                    sAj[(sk0 + 4 * i + 0) * 32 + sr] = tmp[i].x;
                    sAj[(sk0 + 4 * i + 1) * 32 + sr] = tmp[i].y;
                    sAj[(sk0 + 4 * i + 2) * 32 + sr] = tmp[i].z;
                    sAj[(sk0 + 4 * i + 3) * 32 + sr] = tmp[i].w;
                }
            }
            barj(barid);
#pragma unroll
            for (int i = 0; i < 4; i++) {
                if (kb == 0) {
                    acc[i][0].f[0] = bv.x; acc[i][0].f[1] = bv.y;
                    acc[i][1].f[0] = bv.z; acc[i][1].f[1] = bv.w;
                } else { acc[i][0].u = 0ull; acc[i][1].u = 0ull; }
            }
            {
                float4 a_cur = *reinterpret_cast<const float4*>(&sAj[kb * 32 + ty * 4]);
                ulonglong2 b_cur = *reinterpret_cast<const ulonglong2*>(&sWi[kb * 64 + tx * 4]);
#pragma unroll 8
                for (int k = kb; k < kb + 127; k++) {
                    float4 a_nxt = *reinterpret_cast<const float4*>(&sAj[(k + 1) * 32 + ty * 4]);
                    ulonglong2 b_nxt = *reinterpret_cast<const ulonglong2*>(&sWi[(k + 1) * 64 + tx * 4]);
                    unsigned long long a0 = dupr(a_cur.x), a1 = dupr(a_cur.y);
                    unsigned long long a2 = dupr(a_cur.z), a3 = dupr(a_cur.w);
                    fma2(acc[0][0].u, a0, b_cur.x); fma2(acc[0][1].u, a0, b_cur.y);
                    fma2(acc[1][0].u, a1, b_cur.x); fma2(acc[1][1].u, a1, b_cur.y);
                    fma2(acc[2][0].u, a2, b_cur.x); fma2(acc[2][1].u, a2, b_cur.y);
                    fma2(acc[3][0].u, a3, b_cur.x); fma2(acc[3][1].u, a3, b_cur.y);
                    a_cur = a_nxt; b_cur = b_nxt;
                }
                unsigned long long a0 = dupr(a_cur.x), a1 = dupr(a_cur.y);
                unsigned long long a2 = dupr(a_cur.z), a3 = dupr(a_cur.w);
                fma2(acc[0][0].u, a0, b_cur.x); fma2(acc[0][1].u, a0, b_cur.y);
                fma2(acc[1][0].u, a1, b_cur.x); fma2(acc[1][1].u, a1, b_cur.y);
                fma2(acc[2][0].u, a2, b_cur.x); fma2(acc[2][1].u, a2, b_cur.y);
                fma2(acc[3][0].u, a3, b_cur.x); fma2(acc[3][1].u, a3, b_cur.y);
            }
            barj(barid);
            flag_wait(g, (unsigned)(t + 2));
        }
    }

    // final h must end in buffer 0 for k_latctx (ping-pong parity varies per group)
    if ((TG & 1) && lower) {
#pragma unroll
        for (int i = 0; i < 4; i++)
            g_h[0][(b0 + ty * 4 + i) * NH + j] = rh[i];
    }
}

// ---------------- decoder scan: pred GEMM moved to the wait window -----------
// Iteration t stages h[t] (h[0]=ctx). t<NT: gates GEMM (NO pred loads -> 3 LDS
// wf/warp/k, FMA-bound), reduce, epilogue h[t+1], signal. Then pred GEMM from
// the still-staged sAj (h[t] @ Wop) -> recon[t-1] for t>=1, inside the wait
// window. Iteration t=NT is pred-only (recon[NT-1] from h[NT]).
__global__ void __launch_bounds__(512, 1) k_dscan(unsigned ebase,
                                                  const float* __restrict__ Wop,
                                                  const float* __restrict__ bop,
                                                  float* __restrict__ out) {
    extern __shared__ float sm[];
    float* sW  = sm;                       // [256 k][64]             64 KB
    float* sA  = sm + NH * 64;             // 2 x [256 k][32 rows]    64 KB
    float* sR  = sA + 2 * NH * 32;         // 2 x [16][128] partials  16 KB
    float* sRp = sR + 2 * 16 * 128;        // 2 x [128] pred partials  1 KB
    float* sP  = sRp + 2 * 128;            // [256 k][4] Wop tile      4 KB

    const int tid  = threadIdx.x;
    const int jid  = tid >> 8;
    const int jtid = tid & 255;
    const int barid = 1 + jid;
    const int by = blockIdx.x >> 3;
    const int g  = (blockIdx.x & 7) + jid * 8;
    const int b0 = g * 32;
    const int c0 = by * 64;
    const int sub = jtid & 127;
    const int kb  = (jtid >> 7) * 128;
    const int tx = sub & 15, ty = sub >> 4;
    const int j  = (c0 >> 2) + tx;
    const int pr = sub >> 2, pc = sub & 3;
    const int sr  = jtid & 31;
    const int sk0 = (jtid >> 5) * 32;
    float* sAj  = sA + jid * NH * 32;
    float* sRj  = sR + jid * 16 * 128;
    float* sRpj = sRp + jid * 128;
    const bool lower = (jtid < 128);
    const int ob = g_perm[b0 + pr];        // original row for recon stores

    for (int q = tid; q < NH * 16; q += 512) {
        int k = q >> 4, cc = (q & 15) * 4;
        *reinterpret_cast<float4*>(&sW[k * 64 + cc]) =
            *reinterpret_cast<const float4*>(&g_Wr_d[(size_t)k * NG + c0 + cc]);
    }
    for (int q = tid; q < NH * 4; q += 512)
        sP[q] = Wop[(q >> 2) * NOBS + by * 4 + (q & 3)];
    const float4 bv = *reinterpret_cast<const float4*>(&g_br_d[c0 + tx * 4]);
    const float bopv = bop[by * 4 + pc];

    float rc[4], rh[4];
#pragma unroll
    for (int i = 0; i < 4; i++) {
        const int b = b0 + ty * 4 + i;
        float v = g_h[0][b * NH + j];
        rc[i] = v; rh[i] = v;
    }
    __syncthreads();

    for (int t = 0; t <= NT; t++) {
        const float* __restrict__ h_in = g_h[t & 1];
        float* __restrict__ h_out = g_h[(t & 1) ^ 1];

        // ---- stage h[t] tile ----
        {
            float4 tmp[8];
#pragma unroll
            for (int i = 0; i < 8; i++)
                tmp[i] = *reinterpret_cast<const float4*>(
                    &h_in[(size_t)(b0 + sr) * NH + sk0 + 4 * i]);
#pragma unroll
            for (int i = 0; i < 8; i++) {
                sAj[(sk0 + 4 * i + 0) * 32 + sr] = tmp[i].x;
                sAj[(sk0 + 4 * i + 1) * 32 + sr] = tmp[i].y;
                sAj[(sk0 + 4 * i + 2) * 32 + sr] = tmp[i].z;
                sAj[(sk0 + 4 * i + 3) * 32 + sr] = tmp[i].w;
            }
        }
        barj(barid);

        if (t < NT) {
            // ---- gates GEMM (no pred loads) ----
            F2U acc[4][2];
#pragma unroll
            for (int i = 0; i < 4; i++) { acc[i][0].u = 0ull; acc[i][1].u = 0ull; }

            float4 a_cur = *reinterpret_cast<const float4*>(&sAj[kb * 32 + ty * 4]);
            ulonglong2 b_cur = *reinterpret_cast<const ulonglong2*>(&sW[kb * 64 + tx * 4]);
#pragma unroll 8
            for (int k = kb; k < kb + 127; k++) {
                float4 a_nxt = *reinterpret_cast<const float4*>(&sAj[(k + 1) * 32 + ty * 4]);
                ulonglong2 b_nxt = *reinterpret_cast<const ulonglong2*>(&sW[(k + 1) * 64 + tx * 4]);
                unsigned long long a0 = dupr(a_cur.x), a1 = dupr(a_cur.y);
                unsigned long long a2 = dupr(a_cur.z), a3 = dupr(a_cur.w);
                fma2(acc[0][0].u, a0, b_cur.x); fma2(acc[0][1].u, a0, b_cur.y);
                fma2(acc[1][0].u, a1, b_cur.x); fma2(acc[1][1].u, a1, b_cur.y);
                fma2(acc[2][0].u, a2, b_cur.x); fma2(acc[2][1].u, a2, b_cur.y);
                fma2(acc[3][0].u, a3, b_cur.x); fma2(acc[3][1].u, a3, b_cur.y);
                a_cur = a_nxt; b_cur = b_nxt;
            }
            {
                unsigned long long a0 = dupr(a_cur.x), a1 = dupr(a_cur.y);
                unsigned long long a2 = dupr(a_cur.z), a3 = dupr(a_cur.w);
                fma2(acc[0][0].u, a0, b_cur.x); fma2(acc[0][1].u, a0, b_cur.y);
                fma2(acc[1][0].u, a1, b_cur.x); fma2(acc[1][1].u, a1, b_cur.y);
                fma2(acc[2][0].u, a2, b_cur.x); fma2(acc[2][1].u, a2, b_cur.y);
                fma2(acc[3][0].u, a3, b_cur.x); fma2(acc[3][1].u, a3, b_cur.y);
            }

            if (!lower) {
#pragma unroll
                for (int i = 0; i < 4; i++) {
                    sRj[(i * 4 + 0) * 128 + sub] = acc[i][0].f[0];
                    sRj[(i * 4 + 1) * 128 + sub] = acc[i][0].f[1];
                    sRj[(i * 4 + 2) * 128 + sub] = acc[i][1].f[0];
                    sRj[(i * 4 + 3) * 128 + sub] = acc[i][1].f[1];
                }
            }
            barj(barid);

            if (lower) {
#pragma unroll
                for (int i = 0; i < 4; i++) {
                    const int b = b0 + ty * 4 + i;
                    float zi = acc[i][0].f[0] + sRj[(i * 4 + 0) * 128 + sub] + bv.x;
                    float zf = acc[i][0].f[1] + sRj[(i * 4 + 1) * 128 + sub] + bv.y;
                    float zg = acc[i][1].f[0] + sRj[(i * 4 + 2) * 128 + sub] + bv.z;
                    float zo = acc[i][1].f[1] + sRj[(i * 4 + 3) * 128 + sub] + bv.w;
                    float ig = fsig(zi), fg = fsig(zf), gg = ftanh(zg), og = fsig(zo);
                    float nc = fg * rc[i] + ig * gg;
                    float nh = og * ftanh(nc);
                    rc[i] = nc; rh[i] = nh;
                    h_out[b * NH + j] = nh;
                }
            }
            barj(barid);
            if (jtid == 0) flag_signal(g, by, ebase + (unsigned)(t + 1));
        }

        // ---- pred GEMM from still-staged sAj = h[t] -> recon[t-1] ----
        if (t >= 1) {
            float accp = 0.0f;
            float p_cur = sAj[kb * 32 + pr], w_cur = sP[kb * 4 + pc];
#pragma unroll 8
            for (int k = kb; k < kb + 127; k++) {
                float p_nxt = sAj[(k + 1) * 32 + pr];
                float w_nxt = sP[(k + 1) * 4 + pc];
                accp = fmaf(p_cur, w_cur, accp);
                p_cur = p_nxt; w_cur = w_nxt;
            }
            accp = fmaf(p_cur, w_cur, accp);
            if (!lower) sRpj[sub] = accp;
            barj(barid);
            if (lower)
                out[((size_t)ob * NT + (t - 1)) * NOBS + by * 4 + pc] =
                    accp + sRpj[sub] + bopv;
        }

        if (t < NT) flag_wait(g, ebase + (unsigned)(t + 1));
    }
}

// ---------------- latent + context (fused; de-permute latent store) ----------
__global__ void k_latctx(const float* __restrict__ Wlp, const float* __restrict__ blp,
                         const float* __restrict__ Wle, const float* __restrict__ ble,
                         float* __restrict__ out) {
    __shared__ float slat[NLAT];
    const int b = blockIdx.x, tid = threadIdx.x;
    const int l = tid >> 4, sub = tid & 15;
    const float* h = g_h[0];
    float s = 0.0f;
    for (int k = sub; k < NH; k += 16) s += h[b * NH + k] * Wlp[k * NLAT + l];
#pragma unroll
    for (int off = 8; off; off >>= 1) s += __shfl_xor_sync(0xffffffffu, s, off);
    if (sub == 0) {
        float v = s + blp[l];
        slat[l] = v;
        out[(size_t)NB * NT * NOBS + (size_t)g_perm[b] * NLAT + l] = v;
    }
    __syncthreads();
    float s2 = ble[tid];
#pragma unroll
    for (int l2 = 0; l2 < NLAT; l2++) s2 += slat[l2] * Wle[l2 * NH + tid];
    g_h[0][b * NH + tid] = s2 > 0.0f ? s2 : 0.01f * s2;
}

// ---------------- driver -----------------------------------------------------
extern "C" void kernel_launch(void* const* d_in, const int* in_sizes, int n_in,
                              void* d_out, int out_size) {
    (void)in_sizes; (void)n_in; (void)out_size;
    const float* x    = (const float*)d_in[0];
    const void*  mask = d_in[1];
    const float* Wip  = (const float*)d_in[2];
    const float* bip  = (const float*)d_in[3];
    const float* Wi_e = (const float*)d_in[4];
    const float* Wh_e = (const float*)d_in[5];
    const float* b_e  = (const float*)d_in[6];
    const float* Wlp  = (const float*)d_in[7];
    const float* blp  = (const float*)d_in[8];
    const float* Wle  = (const float*)d_in[9];
    const float* ble  = (const float*)d_in[10];
    const float* Wi_d = (const float*)d_in[11];
    const float* Wh_d = (const float*)d_in[12];
    const float* b_d  = (const float*)d_in[13];
    const float* Wop  = (const float*)d_in[14];
    const float* bop  = (const float*)d_in[15];
    float* out = (float*)d_out;

    const size_t smem_e = (size_t)(NH * 64 * 2 + 2 * NH * 32 + 2 * 16 * 128) * sizeof(float);
    const size_t smem_d = (size_t)(NH * 64 + 2 * NH * 32 + 2 * 16 * 128 + 2 * 128 + NH * 4)
                          * sizeof(float);
    cudaFuncSetAttribute(k_escan, cudaFuncAttributeMaxDynamicSharedMemorySize, (int)smem_e);
    cudaFuncSetAttribute(k_dscan, cudaFuncAttributeMaxDynamicSharedMemorySize, (int)smem_d);

    // 6 graph nodes total
    k_setup<<<1024, 256>>>(mask, Wi_e, Wh_e, Wi_d, Wh_d, b_e, b_d);
    k_sort<<<1, NB>>>();
    k_inproj<<<dim3(NB * NT / 64, NH / 64), 256>>>(x, Wip, bip);
    k_escan<<<NBLK, 512, smem_e>>>();
    k_latctx<<<NB, 256>>>(Wlp, blp, Wle, ble, out);
    k_dscan<<<NBLK, 512, smem_d>>>(513u, Wop, bop, out);
}